// round 7
// baseline (speedup 1.0000x reference)
#include <cuda_runtime.h>
#include <cuda_bf16.h>
#include <cstdint>

// Problem constants
#define NNODES 4096       // B*N = 8*512
#define KNBR   16
#define CPOOL  256
#define GDIM   128
#define INDIM  384        // CPOOL + GDIM
#define LDIM   512
#define OUTLD  1920       // 384 + 3*512
#define WSTRIDE (1024 * 512)

// ---------------- device scratch (no allocations allowed) ----------------
__device__ float g_D   [NNODES * 1024];
__device__ float g_biasL[3 * 1024];
__device__ __align__(16) __nv_bfloat16 g_X0h[NNODES * INDIM];
__device__ __align__(16) __nv_bfloat16 g_X0l[NNODES * INDIM];
__device__ __align__(16) __nv_bfloat16 g_Xh [NNODES * LDIM];
__device__ __align__(16) __nv_bfloat16 g_Xl [NNODES * LDIM];
__device__ __align__(16) __nv_bfloat16 g_Wh [3 * WSTRIDE];
__device__ __align__(16) __nv_bfloat16 g_Wl [3 * WSTRIDE];

// ======================= helpers =======================
__device__ __forceinline__ uint32_t smem_u32(const void* p) {
    uint32_t a;
    asm("{ .reg .u64 t; cvta.to.shared.u64 t, %1; cvt.u32.u64 %0, t; }"
        : "=r"(a) : "l"(p));
    return a;
}
__device__ __forceinline__ uint32_t sw64(uint32_t o) {   // SW64 swizzle for 64B rows
    return o ^ ((o >> 3) & 0x30);
}
__device__ __forceinline__ void cp16(uint32_t dst, const void* src) {
    asm volatile("cp.async.cg.shared.global [%0], [%1], 16;" :: "r"(dst), "l"(src));
}
#define CP_COMMIT() asm volatile("cp.async.commit_group;" ::: "memory")
#define CP_WAIT(n)  asm volatile("cp.async.wait_group %0;" :: "n"(n) : "memory")

#define LDSM4(r, a) \
    asm volatile("ldmatrix.sync.aligned.m8n8.x4.shared.b16 {%0,%1,%2,%3}, [%4];" \
        : "=r"((r)[0]), "=r"((r)[1]), "=r"((r)[2]), "=r"((r)[3]) : "r"(a))

#define MMA16816(d, a, b0, b1) \
    asm volatile("mma.sync.aligned.m16n8k16.row.col.f32.bf16.bf16.f32 " \
        "{%0,%1,%2,%3}, {%4,%5,%6,%7}, {%8,%9}, {%0,%1,%2,%3};" \
        : "+f"((d)[0]), "+f"((d)[1]), "+f"((d)[2]), "+f"((d)[3]) \
        : "r"((a)[0]), "r"((a)[1]), "r"((a)[2]), "r"((a)[3]), "r"(b0), "r"(b1))

__device__ __forceinline__ void split_bf16(float v, __nv_bfloat16& h, __nv_bfloat16& l) {
    h = __float2bfloat16(v);
    l = __float2bfloat16(v - __bfloat162float(h));
}

// ======================= mma.sync GEMM =======================
// D(4096 x 1024) = X(4096 x Kin) @ W(1024 x Kin)^T + bias
// bf16 hi/lo split, 3-pass compensation, fp32 accumulation.
// CTA tile 128(M) x 256(N), BK=32, 512 threads (16 warps, warp tile 32x64),
// cp.async double buffer. Grid = (4, 32) = 128 CTAs = one full wave.
// smem per stage (48KB): Ah(8K) | Al(8K) | Bh(16K) | Bl(16K), rows of 64B, SW64.
#define ARR_A   8192
#define ARR_B   16384
#define OFF_AH  0
#define OFF_AL  (ARR_A)
#define OFF_BH  (2 * ARR_A)
#define OFF_BL  (2 * ARR_A + ARR_B)
#define STG_BYTES (2 * ARR_A + 2 * ARR_B)   // 49152
#define GEMM_SMEM (2 * STG_BYTES)           // 98304

__global__ __launch_bounds__(512) void gemm_mma(
    const __nv_bfloat16* __restrict__ Ah, const __nv_bfloat16* __restrict__ Al,
    const __nv_bfloat16* __restrict__ Bh, const __nv_bfloat16* __restrict__ Bl,
    const float* __restrict__ bias,
    float* __restrict__ C,      // ldc = 1024
    int Kin)
{
    extern __shared__ char smem[];
    const uint32_t sb  = smem_u32(smem);
    const int tid  = threadIdx.x;
    const int lane = tid & 31;
    const int wid  = tid >> 5;               // 0..15
    const int bm   = blockIdx.y * 128;
    const int bn   = blockIdx.x * 256;
    const int m0   = (wid & 3) * 32;         // warp m-offset in tile
    const int n0   = (wid >> 2) * 64;        // warp n-offset in tile (0..192)

    // cp.async chunk mapping (16B chunks, 4 segs of 16B per 64B row):
    //  A: 128 rows * 4 segs = 512 chunks -> 1 per thread
    //  B: 256 rows * 4 segs = 1024 chunks -> 2 per thread (rows r, r+128)
    const int rA  = tid >> 2;                // 0..127
    const int seg = tid & 3;                 // 0..3

    const uint32_t offA  = sw64((uint32_t)(rA * 64 + seg * 16));
    const uint32_t offB0 = offA;                                   // row rA
    const uint32_t offB1 = sw64((uint32_t)((rA + 128) * 64 + seg * 16));

    const __nv_bfloat16* ga_h = Ah + (size_t)(bm + rA) * Kin + seg * 8;
    const __nv_bfloat16* ga_l = Al + (size_t)(bm + rA) * Kin + seg * 8;
    const __nv_bfloat16* gb_h0 = Bh + (size_t)(bn + rA) * Kin + seg * 8;
    const __nv_bfloat16* gb_l0 = Bl + (size_t)(bn + rA) * Kin + seg * 8;
    const __nv_bfloat16* gb_h1 = Bh + (size_t)(bn + rA + 128) * Kin + seg * 8;
    const __nv_bfloat16* gb_l1 = Bl + (size_t)(bn + rA + 128) * Kin + seg * 8;

    const int nk = Kin / 32;

    // ---- issue stage 0 ----
    {
        const uint32_t bufb = sb;
        cp16(bufb + OFF_AH + offA,  ga_h);
        cp16(bufb + OFF_AL + offA,  ga_l);
        cp16(bufb + OFF_BH + offB0, gb_h0);
        cp16(bufb + OFF_BH + offB1, gb_h1);
        cp16(bufb + OFF_BL + offB0, gb_l0);
        cp16(bufb + OFF_BL + offB1, gb_l1);
        CP_COMMIT();
    }

    float acc[2][8][4];
    #pragma unroll
    for (int i = 0; i < 2; i++)
        #pragma unroll
        for (int j = 0; j < 8; j++)
            #pragma unroll
            for (int q = 0; q < 4; q++)
                acc[i][j][q] = 0.0f;

    // ldmatrix per-lane address components
    const int a_row = lane & 15;             // row within m16 tile
    const int a_kh  = (lane >> 4) & 1;       // k half (0/8)
    const int b_row = ((lane >> 4) << 3) + (lane & 7);  // row within n16 pair
    const int b_kh  = (lane >> 3) & 1;

    for (int s = 0; s < nk; s++) {
        const uint32_t bufb = sb + (uint32_t)(s & 1) * STG_BYTES;

        if (s + 1 < nk) {
            const uint32_t nb = sb + (uint32_t)((s + 1) & 1) * STG_BYTES;
            const int kb = (s + 1) * 32;
            cp16(nb + OFF_AH + offA,  ga_h + kb);
            cp16(nb + OFF_AL + offA,  ga_l + kb);
            cp16(nb + OFF_BH + offB0, gb_h0 + kb);
            cp16(nb + OFF_BH + offB1, gb_h1 + kb);
            cp16(nb + OFF_BL + offB0, gb_l0 + kb);
            cp16(nb + OFF_BL + offB1, gb_l1 + kb);
            CP_COMMIT();
            CP_WAIT(1);
        } else {
            CP_WAIT(0);
        }
        __syncthreads();

        #pragma unroll
        for (int kk = 0; kk < 2; kk++) {
            uint32_t fah[2][4], fal[2][4];
            #pragma unroll
            for (int mt = 0; mt < 2; mt++) {
                const uint32_t off =
                    sw64((uint32_t)((m0 + mt * 16 + a_row) * 64 + kk * 32 + a_kh * 16));
                LDSM4(fah[mt], bufb + OFF_AH + off);
                LDSM4(fal[mt], bufb + OFF_AL + off);
            }
            uint32_t fbh[4][4], fbl[4][4];
            #pragma unroll
            for (int nt = 0; nt < 4; nt++) {
                const uint32_t off =
                    sw64((uint32_t)((n0 + nt * 16 + b_row) * 64 + kk * 32 + b_kh * 16));
                LDSM4(fbh[nt], bufb + OFF_BH + off);
                LDSM4(fbl[nt], bufb + OFF_BL + off);
            }
            #pragma unroll
            for (int mt = 0; mt < 2; mt++) {
                #pragma unroll
                for (int ni = 0; ni < 8; ni++) {
                    const uint32_t bh0 = fbh[ni >> 1][(ni & 1) * 2];
                    const uint32_t bh1 = fbh[ni >> 1][(ni & 1) * 2 + 1];
                    const uint32_t bl0 = fbl[ni >> 1][(ni & 1) * 2];
                    const uint32_t bl1 = fbl[ni >> 1][(ni & 1) * 2 + 1];
                    MMA16816(acc[mt][ni], fah[mt], bh0, bh1);
                    MMA16816(acc[mt][ni], fah[mt], bl0, bl1);
                    MMA16816(acc[mt][ni], fal[mt], bh0, bh1);
                }
            }
        }
        __syncthreads();
    }

    // ---- epilogue: write D with bias ----
    #pragma unroll
    for (int mt = 0; mt < 2; mt++) {
        const int r = bm + m0 + mt * 16 + (lane >> 2);
        #pragma unroll
        for (int ni = 0; ni < 8; ni++) {
            const int col = bn + n0 + ni * 8 + (lane & 3) * 2;
            const float b0 = bias[col], b1 = bias[col + 1];
            float2 v0 = { acc[mt][ni][0] + b0, acc[mt][ni][1] + b1 };
            float2 v1 = { acc[mt][ni][2] + b0, acc[mt][ni][3] + b1 };
            *(float2*)(C + (size_t)r * 1024 + col)       = v0;
            *(float2*)(C + (size_t)(r + 8) * 1024 + col) = v1;
        }
    }
}

// ======================= fused prologue =======================
// Per node: geo MLP (7->128 relu, 128->128 relu), copy pooled, write
// out[:, 0:384], and produce bf16 hi/lo of X0. One block per node.
__global__ __launch_bounds__(128) void fused_pre(
    const float* __restrict__ rois,
    const float* __restrict__ pooled,
    const float* __restrict__ gW1, const float* __restrict__ gb1,
    const float* __restrict__ gW2, const float* __restrict__ gb2,
    float* __restrict__ out,
    __nv_bfloat16* __restrict__ X0h, __nv_bfloat16* __restrict__ X0l)
{
    __shared__ float s_roi[8];
    __shared__ float s_h[GDIM];

    const int n   = blockIdx.x;
    const int tid = threadIdx.x;

    if (tid < 7) s_roi[tid] = rois[n * 7 + tid];
    __syncthreads();

    // layer 1: hidden = relu(gW1 @ roi + gb1)
    float a1 = gb1[tid];
    #pragma unroll
    for (int j = 0; j < 7; j++) a1 = fmaf(gW1[tid * 7 + j], s_roi[j], a1);
    s_h[tid] = fmaxf(a1, 0.0f);
    __syncthreads();

    // layer 2: g = relu(gW2 @ hidden + gb2)
    float a2 = gb2[tid];
    const float4* w2 = (const float4*)(gW2 + tid * GDIM);
    #pragma unroll
    for (int j = 0; j < GDIM / 4; j++) {
        float4 w = w2[j];
        a2 = fmaf(w.x, s_h[4 * j + 0], a2);
        a2 = fmaf(w.y, s_h[4 * j + 1], a2);
        a2 = fmaf(w.z, s_h[4 * j + 2], a2);
        a2 = fmaf(w.w, s_h[4 * j + 3], a2);
    }
    float g = fmaxf(a2, 0.0f);

    out[(size_t)n * OUTLD + CPOOL + tid] = g;
    __nv_bfloat16 gh, gl;
    split_bf16(g, gh, gl);
    X0h[(size_t)n * INDIM + CPOOL + tid] = gh;
    X0l[(size_t)n * INDIM + CPOOL + tid] = gl;

    // pooled: 2 columns per thread
    #pragma unroll
    for (int c = tid; c < CPOOL; c += 128) {
        float v = pooled[(size_t)n * CPOOL + c];
        out[(size_t)n * OUTLD + c] = v;
        __nv_bfloat16 h, l;
        split_bf16(v, h, l);
        X0h[(size_t)n * INDIM + c] = h;
        X0l[(size_t)n * INDIM + c] = l;
    }
}

// ======================= weight prep (all 3 layers) =======================
// Wcat = [W_l ; W_r - W_l] as bf16 hi/lo; biasL = [0 ; b]. Layer = blockIdx.y.
__global__ void prep_w3(
    const float* __restrict__ W0, const float* __restrict__ b0,
    const float* __restrict__ W1, const float* __restrict__ b1,
    const float* __restrict__ W2, const float* __restrict__ b2,
    __nv_bfloat16* __restrict__ Wh, __nv_bfloat16* __restrict__ Wl,
    float* __restrict__ biasL)
{
    const int layer = blockIdx.y;
    const float* W = (layer == 0) ? W0 : (layer == 1) ? W1 : W2;
    const float* b = (layer == 0) ? b0 : (layer == 1) ? b1 : b2;
    const int Kin  = (layer == 0) ? INDIM : LDIM;

    __nv_bfloat16* wh = Wh + (size_t)layer * WSTRIDE;
    __nv_bfloat16* wl = Wl + (size_t)layer * WSTRIDE;

    int idx = blockIdx.x * blockDim.x + threadIdx.x;
    if (idx < 512 * Kin) {
        int r = idx / Kin, c = idx % Kin;
        float vl = W[(size_t)r * 2 * Kin + c];
        float vr = W[(size_t)r * 2 * Kin + Kin + c];
        float d  = vr - vl;

        __nv_bfloat16 h, l;
        split_bf16(vl, h, l);
        wh[(size_t)r * Kin + c] = h;
        wl[(size_t)r * Kin + c] = l;
        split_bf16(d, h, l);
        wh[(size_t)(512 + r) * Kin + c] = h;
        wl[(size_t)(512 + r) * Kin + c] = l;
    }
    if (idx < 512) {
        biasL[layer * 1024 + idx]       = 0.0f;
        biasL[layer * 1024 + 512 + idx] = b[idx];
    }
}

// ---------------- aggregation + bf16 split of the new features ------------
__global__ __launch_bounds__(128) void aggregate(
    const float* __restrict__ D,
    const int*   __restrict__ src,
    __nv_bfloat16* __restrict__ Xh,  // 4096 x 512
    __nv_bfloat16* __restrict__ Xl,
    float* __restrict__ out,         // 4096 x 1920
    int out_off)
{
    const int n  = blockIdx.x;
    const int f4 = threadIdx.x;   // 0..127

    float4 c = *reinterpret_cast<const float4*>(D + (size_t)n * 1024 + 512 + f4 * 4);
    float4 m = make_float4(0.f, 0.f, 0.f, 0.f);

    #pragma unroll
    for (int k = 0; k < KNBR; k++) {
        int j = src[n * KNBR + k];
        float4 a = *reinterpret_cast<const float4*>(D + (size_t)j * 1024 + f4 * 4);
        m.x = fmaxf(m.x, a.x + c.x);
        m.y = fmaxf(m.y, a.y + c.y);
        m.z = fmaxf(m.z, a.z + c.z);
        m.w = fmaxf(m.w, a.w + c.w);
    }
    *reinterpret_cast<float4*>(out + (size_t)n * OUTLD + out_off + f4 * 4) = m;

    __nv_bfloat16 hx, hy, hz, hw, lx, ly, lz, lw;
    split_bf16(m.x, hx, lx); split_bf16(m.y, hy, ly);
    split_bf16(m.z, hz, lz); split_bf16(m.w, hw, lw);
    __nv_bfloat162 h01, h23, l01, l23;
    h01.x = hx; h01.y = hy; h23.x = hz; h23.y = hw;
    l01.x = lx; l01.y = ly; l23.x = lz; l23.y = lw;

    *reinterpret_cast<__nv_bfloat162*>(Xh + (size_t)n * LDIM + f4 * 4)     = h01;
    *reinterpret_cast<__nv_bfloat162*>(Xh + (size_t)n * LDIM + f4 * 4 + 2) = h23;
    *reinterpret_cast<__nv_bfloat162*>(Xl + (size_t)n * LDIM + f4 * 4)     = l01;
    *reinterpret_cast<__nv_bfloat162*>(Xl + (size_t)n * LDIM + f4 * 4 + 2) = l23;
}

// ---------------------------------------------------------------------------
extern "C" void kernel_launch(void* const* d_in, const int* in_sizes, int n_in,
                              void* d_out, int out_size)
{
    const float* rois   = (const float*)d_in[0];
    const float* pooled = (const float*)d_in[1];
    const int*   edge   = (const int*)  d_in[2];   // (2, 65536): row 0 = src
    const float* gW1    = (const float*)d_in[3];
    const float* gb1    = (const float*)d_in[4];
    const float* gW2    = (const float*)d_in[5];
    const float* gb2    = (const float*)d_in[6];
    const float* fcW[3] = {(const float*)d_in[7], (const float*)d_in[9],  (const float*)d_in[11]};
    const float* fcb[3] = {(const float*)d_in[8], (const float*)d_in[10], (const float*)d_in[12]};
    float* out = (float*)d_out;

    const int* src = edge;

    float *D, *biasL;
    __nv_bfloat16 *X0h, *X0l, *Xh, *Xl, *Wh, *Wl;
    cudaGetSymbolAddress((void**)&D,     g_D);
    cudaGetSymbolAddress((void**)&biasL, g_biasL);
    cudaGetSymbolAddress((void**)&X0h,   g_X0h);
    cudaGetSymbolAddress((void**)&X0l,   g_X0l);
    cudaGetSymbolAddress((void**)&Xh,    g_Xh);
    cudaGetSymbolAddress((void**)&Xl,    g_Xl);
    cudaGetSymbolAddress((void**)&Wh,    g_Wh);
    cudaGetSymbolAddress((void**)&Wl,    g_Wl);

    cudaFuncSetAttribute(gemm_mma, cudaFuncAttributeMaxDynamicSharedMemorySize, GEMM_SMEM);

    // 1) all weight prep (independent of activations)
    prep_w3<<<dim3(1024, 3), 256>>>(
        fcW[0], fcb[0], fcW[1], fcb[1], fcW[2], fcb[2], Wh, Wl, biasL);

    // 2) fused prologue: geo MLP + pooled + out[:, :384] + bf16 split
    fused_pre<<<NNODES, 128>>>(rois, pooled, gW1, gb1, gW2, gb2, out, X0h, X0l);

    // 3) three EdgeConv layers
    const int Kin[3]    = {INDIM, LDIM, LDIM};
    const int outOff[3] = {384, 384 + 512, 384 + 1024};

    for (int l = 0; l < 3; l++) {
        const __nv_bfloat16* Ah = (l == 0) ? X0h : Xh;
        const __nv_bfloat16* Al = (l == 0) ? X0l : Xl;
        gemm_mma<<<dim3(1024 / 256, NNODES / 128), 512, GEMM_SMEM>>>(
            Ah, Al, Wh + (size_t)l * WSTRIDE, Wl + (size_t)l * WSTRIDE,
            biasL + l * 1024, D, Kin[l]);

        aggregate<<<NNODES, 128>>>(D, src, Xh, Xl, out, outOff[l]);
    }
}

// round 8
// speedup vs baseline: 1.5978x; 1.5978x over previous
#include <cuda_runtime.h>
#include <cuda_bf16.h>
#include <cuda_fp16.h>
#include <cstdint>

// Problem constants
#define NNODES 4096       // B*N = 8*512
#define KNBR   16
#define CPOOL  256
#define GDIM   128
#define INDIM  384        // CPOOL + GDIM
#define LDIM   512
#define OUTLD  1920       // 384 + 3*512
#define WSTRIDE (1024 * 512)

// ---------------- device scratch (no allocations allowed) ----------------
__device__ float g_H   [NNODES * GDIM];
__device__ float g_D   [NNODES * 1024];
__device__ float g_biasL[3 * 1024];
__device__ __align__(16) __half g_X0h[NNODES * INDIM];
__device__ __align__(16) __half g_Xh [NNODES * LDIM];
__device__ __align__(16) __half g_Wh [3 * WSTRIDE];
__device__ __align__(16) __half g_Wl [3 * WSTRIDE];

// ======================= helpers =======================
__device__ __forceinline__ uint32_t smem_u32(const void* p) {
    uint32_t a;
    asm("{ .reg .u64 t; cvta.to.shared.u64 t, %1; cvt.u32.u64 %0, t; }"
        : "=r"(a) : "l"(p));
    return a;
}
__device__ __forceinline__ uint32_t sw64(uint32_t o) {   // SW64 swizzle for 64B rows
    return o ^ ((o >> 3) & 0x30);
}
__device__ __forceinline__ void cp16(uint32_t dst, const void* src) {
    asm volatile("cp.async.cg.shared.global [%0], [%1], 16;" :: "r"(dst), "l"(src));
}
#define CP_COMMIT() asm volatile("cp.async.commit_group;" ::: "memory")
#define CP_WAIT(n)  asm volatile("cp.async.wait_group %0;" :: "n"(n) : "memory")

#define LDSM4(r, a) \
    asm volatile("ldmatrix.sync.aligned.m8n8.x4.shared.b16 {%0,%1,%2,%3}, [%4];" \
        : "=r"((r)[0]), "=r"((r)[1]), "=r"((r)[2]), "=r"((r)[3]) : "r"(a))

#define MMAF16(d, a, b0, b1) \
    asm volatile("mma.sync.aligned.m16n8k16.row.col.f32.f16.f16.f32 " \
        "{%0,%1,%2,%3}, {%4,%5,%6,%7}, {%8,%9}, {%0,%1,%2,%3};" \
        : "+f"((d)[0]), "+f"((d)[1]), "+f"((d)[2]), "+f"((d)[3]) \
        : "r"((a)[0]), "r"((a)[1]), "r"((a)[2]), "r"((a)[3]), "r"(b0), "r"(b1))

// ======================= mma.sync GEMM (fp16, 2-pass) ======================
// D(4096 x 1024) = X(4096 x Kin) @ W(1024 x Kin)^T + bias
// A = activations rounded to fp16; W split into fp16 hi + lo (exact).
// D = A*Wh + A*Wl, fp32 accumulation. Dropped term: Al*W ~ 2^-11 relative.
// CTA tile 128x128, BK=32, 8 warps (warp tile 32x64), cp.async double buffer.
// smem per stage (24KB): A(8K) | Bh(8K) | Bl(8K), rows of 64B, SW64.
#define ARR_BYTES (128 * 64)                // 8192
#define STG_BYTES (3 * ARR_BYTES)           // 24576
#define GEMM_SMEM (2 * STG_BYTES)           // 49152

__global__ __launch_bounds__(256) void gemm_mma(
    const __half* __restrict__ A,
    const __half* __restrict__ Bh, const __half* __restrict__ Bl,
    const float* __restrict__ bias,
    float* __restrict__ C,      // ldc = 1024
    int Kin)
{
    extern __shared__ char smem[];
    const uint32_t sb  = smem_u32(smem);
    const int tid  = threadIdx.x;
    const int lane = tid & 31;
    const int wid  = tid >> 5;
    const int bm   = blockIdx.y * 128;
    const int bn   = blockIdx.x * 128;
    const int m0   = (wid & 3) * 32;     // warp m-offset in tile
    const int n0   = (wid >> 2) * 64;    // warp n-offset in tile

    // cp.async chunk mapping: 512 chunks of 16B per array, 2 per thread
    const int r0c = tid >> 2;            // rows 0..63
    const int s0c = tid & 3;             // seg 0..3
    const int r1c = (tid + 256) >> 2;    // rows 64..127

    const __half* gsrc[3] = { A, Bh, Bl };
    const int grow0[3] = { bm, bn, bn };

    uint32_t soff0[3], soff1[3];
    #pragma unroll
    for (int a = 0; a < 3; a++) {
        soff0[a] = a * ARR_BYTES + sw64((uint32_t)(r0c * 64 + s0c * 16));
        soff1[a] = a * ARR_BYTES + sw64((uint32_t)(r1c * 64 + s0c * 16));
    }

    const int nk = Kin / 32;

    // ---- issue stage 0 ----
    {
        const uint32_t bufb = sb;
        #pragma unroll
        for (int a = 0; a < 3; a++) {
            cp16(bufb + soff0[a], gsrc[a] + (size_t)(grow0[a] + r0c) * Kin + s0c * 8);
            cp16(bufb + soff1[a], gsrc[a] + (size_t)(grow0[a] + r1c) * Kin + s0c * 8);
        }
        CP_COMMIT();
    }

    float acc[2][8][4];
    #pragma unroll
    for (int i = 0; i < 2; i++)
        #pragma unroll
        for (int j = 0; j < 8; j++)
            #pragma unroll
            for (int q = 0; q < 4; q++)
                acc[i][j][q] = 0.0f;

    // ldmatrix per-lane address components
    const int a_row = lane & 15;
    const int a_kh  = (lane >> 4) & 1;
    const int b_row = ((lane >> 4) << 3) + (lane & 7);
    const int b_kh  = (lane >> 3) & 1;

    for (int s = 0; s < nk; s++) {
        const uint32_t bufb = sb + (uint32_t)(s & 1) * STG_BYTES;

        if (s + 1 < nk) {
            const uint32_t nb = sb + (uint32_t)((s + 1) & 1) * STG_BYTES;
            const int kb = (s + 1) * 32;
            #pragma unroll
            for (int a = 0; a < 3; a++) {
                cp16(nb + soff0[a], gsrc[a] + (size_t)(grow0[a] + r0c) * Kin + kb + s0c * 8);
                cp16(nb + soff1[a], gsrc[a] + (size_t)(grow0[a] + r1c) * Kin + kb + s0c * 8);
            }
            CP_COMMIT();
            CP_WAIT(1);
        } else {
            CP_WAIT(0);
        }
        __syncthreads();

        #pragma unroll
        for (int kk = 0; kk < 2; kk++) {
            uint32_t fa[2][4];
            #pragma unroll
            for (int mt = 0; mt < 2; mt++) {
                const uint32_t off =
                    sw64((uint32_t)((m0 + mt * 16 + a_row) * 64 + kk * 32 + a_kh * 16));
                LDSM4(fa[mt], bufb + 0 * ARR_BYTES + off);
            }
            uint32_t fbh[4][4], fbl[4][4];
            #pragma unroll
            for (int nt = 0; nt < 4; nt++) {
                const uint32_t off =
                    sw64((uint32_t)((n0 + nt * 16 + b_row) * 64 + kk * 32 + b_kh * 16));
                LDSM4(fbh[nt], bufb + 1 * ARR_BYTES + off);
                LDSM4(fbl[nt], bufb + 2 * ARR_BYTES + off);
            }
            #pragma unroll
            for (int mt = 0; mt < 2; mt++) {
                #pragma unroll
                for (int ni = 0; ni < 8; ni++) {
                    const uint32_t bh0 = fbh[ni >> 1][(ni & 1) * 2];
                    const uint32_t bh1 = fbh[ni >> 1][(ni & 1) * 2 + 1];
                    const uint32_t bl0 = fbl[ni >> 1][(ni & 1) * 2];
                    const uint32_t bl1 = fbl[ni >> 1][(ni & 1) * 2 + 1];
                    MMAF16(acc[mt][ni], fa[mt], bh0, bh1);
                    MMAF16(acc[mt][ni], fa[mt], bl0, bl1);
                }
            }
        }
        __syncthreads();
    }

    // ---- epilogue: write D with bias ----
    #pragma unroll
    for (int mt = 0; mt < 2; mt++) {
        const int r = bm + m0 + mt * 16 + (lane >> 2);
        #pragma unroll
        for (int ni = 0; ni < 8; ni++) {
            const int col = bn + n0 + ni * 8 + (lane & 3) * 2;
            const float b0 = bias[col], b1 = bias[col + 1];
            float2 v0 = { acc[mt][ni][0] + b0, acc[mt][ni][1] + b1 };
            float2 v1 = { acc[mt][ni][2] + b0, acc[mt][ni][3] + b1 };
            *(float2*)(C + (size_t)r * 1024 + col)       = v0;
            *(float2*)(C + (size_t)(r + 8) * 1024 + col) = v1;
        }
    }
}

// ---------------- generic tiled SGEMM (K=7 geo layer) ------
#define TM 64
#define TN 64
#define TK 16

__global__ void sgemm_tn(const float* __restrict__ A, int lda,
                         const float* __restrict__ B, int ldb,
                         const float* __restrict__ bias,
                         float* __restrict__ C, int ldc, int c_off,
                         int M, int N, int K, int do_relu)
{
    __shared__ float Ams[TK][TM];
    __shared__ float Bms[TK][TN];

    const int bm = blockIdx.y * TM;
    const int bn = blockIdx.x * TN;
    const int tx = threadIdx.x;
    const int ty = threadIdx.y;
    const int tid = ty * 16 + tx;

    float acc[4][4] = {};

    for (int k0 = 0; k0 < K; k0 += TK) {
        #pragma unroll
        for (int i = tid; i < TM * TK; i += 256) {
            int m = i / TK, k = i % TK;
            float v = 0.0f;
            int gm = bm + m, gk = k0 + k;
            if (gm < M && gk < K) v = A[(size_t)gm * lda + gk];
            Ams[k][m] = v;
        }
        #pragma unroll
        for (int i = tid; i < TN * TK; i += 256) {
            int n = i / TK, k = i % TK;
            float v = 0.0f;
            int gn = bn + n, gk = k0 + k;
            if (gn < N && gk < K) v = B[(size_t)gn * ldb + gk];
            Bms[k][n] = v;
        }
        __syncthreads();

        #pragma unroll
        for (int kk = 0; kk < TK; kk++) {
            float4 av = *reinterpret_cast<const float4*>(&Ams[kk][ty * 4]);
            float4 bv = *reinterpret_cast<const float4*>(&Bms[kk][tx * 4]);
            float a[4] = {av.x, av.y, av.z, av.w};
            float b[4] = {bv.x, bv.y, bv.z, bv.w};
            #pragma unroll
            for (int i = 0; i < 4; i++)
                #pragma unroll
                for (int j = 0; j < 4; j++)
                    acc[i][j] = fmaf(a[i], b[j], acc[i][j]);
        }
        __syncthreads();
    }

    #pragma unroll
    for (int i = 0; i < 4; i++) {
        int m = bm + ty * 4 + i;
        if (m >= M) continue;
        #pragma unroll
        for (int j = 0; j < 4; j++) {
            int n = bn + tx * 4 + j;
            if (n >= N) continue;
            float v = acc[i][j];
            if (bias) v += bias[n];
            if (do_relu) v = fmaxf(v, 0.0f);
            C[(size_t)m * ldc + c_off + n] = v;
        }
    }
}

// ---------------- f32x2 SGEMM (geo layer 2, K=128) ----------------
#define BM 128
#define BN 64
#define BK 16

__global__ __launch_bounds__(256) void sgemm_f2(
    const float* __restrict__ A, int lda,
    const float* __restrict__ B, int ldb,
    const float* __restrict__ bias,
    float* __restrict__ C, int ldc, int c_off,
    int K, int do_relu)
{
    __shared__ float As[2][BK][BM];
    __shared__ float Bs[2][BK][BN];

    const int tid = threadIdx.x;
    const int tx  = tid & 15;
    const int ty  = tid >> 4;
    const int bm  = blockIdx.y * BM;
    const int bn  = blockIdx.x * BN;

    const int am  = tid >> 1;
    const int ak  = (tid & 1) * 8;
    const int bnr = tid >> 2;
    const int bk  = (tid & 3) * 4;

    const float* Aptr = A + (size_t)(bm + am) * lda + ak;
    const float* Bptr = B + (size_t)(bn + bnr) * ldb + bk;

    float4 ra0 = *(const float4*)(Aptr);
    float4 ra1 = *(const float4*)(Aptr + 4);
    float4 rb  = *(const float4*)(Bptr);

    As[0][ak + 0][am] = ra0.x;  As[0][ak + 1][am] = ra0.y;
    As[0][ak + 2][am] = ra0.z;  As[0][ak + 3][am] = ra0.w;
    As[0][ak + 4][am] = ra1.x;  As[0][ak + 5][am] = ra1.y;
    As[0][ak + 6][am] = ra1.z;  As[0][ak + 7][am] = ra1.w;
    Bs[0][bk + 0][bnr] = rb.x;  Bs[0][bk + 1][bnr] = rb.y;
    Bs[0][bk + 2][bnr] = rb.z;  Bs[0][bk + 3][bnr] = rb.w;

    unsigned long long acc[4][4];
    #pragma unroll
    for (int i = 0; i < 4; i++)
        #pragma unroll
        for (int j = 0; j < 4; j++)
            acc[i][j] = 0ull;

    const int nk = K / BK;
    int buf = 0;
    __syncthreads();

    for (int kt = 0; kt < nk; kt++) {
        const bool has_next = (kt + 1 < nk);
        if (has_next) {
            const float* Ap = Aptr + (kt + 1) * BK;
            ra0 = *(const float4*)(Ap);
            ra1 = *(const float4*)(Ap + 4);
            rb  = *(const float4*)(Bptr + (kt + 1) * BK);
        }

        #pragma unroll
        for (int kk = 0; kk < BK; kk++) {
            ulonglong2 av0 = *(const ulonglong2*)&As[buf][kk][ty * 8];
            ulonglong2 av1 = *(const ulonglong2*)&As[buf][kk][ty * 8 + 4];
            unsigned long long a0 = av0.x, a1 = av0.y, a2 = av1.x, a3 = av1.y;

            float4 bq = *(const float4*)&Bs[buf][kk][tx * 4];
            unsigned long long b0, b1, b2, b3;
            asm("mov.b64 %0, {%1, %1};" : "=l"(b0) : "f"(bq.x));
            asm("mov.b64 %0, {%1, %1};" : "=l"(b1) : "f"(bq.y));
            asm("mov.b64 %0, {%1, %1};" : "=l"(b2) : "f"(bq.z));
            asm("mov.b64 %0, {%1, %1};" : "=l"(b3) : "f"(bq.w));

            #define FF2(d, a, b) \
                asm("fma.rn.f32x2 %0, %1, %2, %0;" : "+l"(d) : "l"(a), "l"(b))
            FF2(acc[0][0], a0, b0); FF2(acc[0][1], a0, b1);
            FF2(acc[0][2], a0, b2); FF2(acc[0][3], a0, b3);
            FF2(acc[1][0], a1, b0); FF2(acc[1][1], a1, b1);
            FF2(acc[1][2], a1, b2); FF2(acc[1][3], a1, b3);
            FF2(acc[2][0], a2, b0); FF2(acc[2][1], a2, b1);
            FF2(acc[2][2], a2, b2); FF2(acc[2][3], a2, b3);
            FF2(acc[3][0], a3, b0); FF2(acc[3][1], a3, b1);
            FF2(acc[3][2], a3, b2); FF2(acc[3][3], a3, b3);
            #undef FF2
        }

        if (has_next) {
            const int nb = buf ^ 1;
            As[nb][ak + 0][am] = ra0.x;  As[nb][ak + 1][am] = ra0.y;
            As[nb][ak + 2][am] = ra0.z;  As[nb][ak + 3][am] = ra0.w;
            As[nb][ak + 4][am] = ra1.x;  As[nb][ak + 5][am] = ra1.y;
            As[nb][ak + 6][am] = ra1.z;  As[nb][ak + 7][am] = ra1.w;
            Bs[nb][bk + 0][bnr] = rb.x;  Bs[nb][bk + 1][bnr] = rb.y;
            Bs[nb][bk + 2][bnr] = rb.z;  Bs[nb][bk + 3][bnr] = rb.w;
            __syncthreads();
            buf = nb;
        }
    }

    #pragma unroll
    for (int mp = 0; mp < 4; mp++) {
        const int r0 = bm + ty * 8 + mp * 2;
        #pragma unroll
        for (int j = 0; j < 4; j++) {
            const int n = bn + tx * 4 + j;
            float lo, hi;
            asm("mov.b64 {%0, %1}, %2;" : "=f"(lo), "=f"(hi) : "l"(acc[mp][j]));
            float bv = bias ? bias[n] : 0.0f;
            lo += bv; hi += bv;
            if (do_relu) { lo = fmaxf(lo, 0.0f); hi = fmaxf(hi, 0.0f); }
            C[(size_t)r0 * ldc + c_off + n]       = lo;
            C[(size_t)(r0 + 1) * ldc + c_off + n] = hi;
        }
    }
}

// ======================= weight prep (all 3 layers, fp16 hi/lo) ============
__global__ void prep_w3(
    const float* __restrict__ W0, const float* __restrict__ b0,
    const float* __restrict__ W1, const float* __restrict__ b1,
    const float* __restrict__ W2, const float* __restrict__ b2,
    __half* __restrict__ Wh, __half* __restrict__ Wl,
    float* __restrict__ biasL)
{
    const int layer = blockIdx.y;
    const float* W = (layer == 0) ? W0 : (layer == 1) ? W1 : W2;
    const float* b = (layer == 0) ? b0 : (layer == 1) ? b1 : b2;
    const int Kin  = (layer == 0) ? INDIM : LDIM;

    __half* wh = Wh + (size_t)layer * WSTRIDE;
    __half* wl = Wl + (size_t)layer * WSTRIDE;

    int idx = blockIdx.x * blockDim.x + threadIdx.x;
    if (idx < 512 * Kin) {
        int r = idx / Kin, c = idx % Kin;
        float vl = W[(size_t)r * 2 * Kin + c];
        float vr = W[(size_t)r * 2 * Kin + Kin + c];
        float d  = vr - vl;

        __half h = __float2half_rn(vl);
        wh[(size_t)r * Kin + c] = h;
        wl[(size_t)r * Kin + c] = __float2half_rn(vl - __half2float(h));
        h = __float2half_rn(d);
        wh[(size_t)(512 + r) * Kin + c] = h;
        wl[(size_t)(512 + r) * Kin + c] = __float2half_rn(d - __half2float(h));
    }
    if (idx < 512) {
        biasL[layer * 1024 + idx]       = 0.0f;
        biasL[layer * 1024 + 512 + idx] = b[idx];
    }
}

// ------------- finish prologue: pooled copy + fp16 convert of X0 ----------
// Requires out[:,256:384] already written by sgemm_f2.
__global__ void finish_pre(const float* __restrict__ pooled,
                           float* __restrict__ out,
                           __half* __restrict__ X0h)
{
    int idx = blockIdx.x * blockDim.x + threadIdx.x;
    if (idx >= NNODES * INDIM) return;
    int n = idx / INDIM;
    int c = idx - n * INDIM;
    float v;
    if (c < CPOOL) {
        v = pooled[(size_t)n * CPOOL + c];
        out[(size_t)n * OUTLD + c] = v;
    } else {
        v = out[(size_t)n * OUTLD + c];
    }
    X0h[idx] = __float2half_rn(v);
}

// ---------------- aggregation + fp16 convert of new features --------------
__global__ __launch_bounds__(128) void aggregate(
    const float* __restrict__ D,
    const int*   __restrict__ src,
    __half* __restrict__ Xh,         // 4096 x 512
    float* __restrict__ out,         // 4096 x 1920
    int out_off)
{
    const int n  = blockIdx.x;
    const int f4 = threadIdx.x;   // 0..127

    float4 c = *reinterpret_cast<const float4*>(D + (size_t)n * 1024 + 512 + f4 * 4);
    float4 m = make_float4(0.f, 0.f, 0.f, 0.f);

    #pragma unroll
    for (int k = 0; k < KNBR; k++) {
        int j = src[n * KNBR + k];
        float4 a = *reinterpret_cast<const float4*>(D + (size_t)j * 1024 + f4 * 4);
        m.x = fmaxf(m.x, a.x + c.x);
        m.y = fmaxf(m.y, a.y + c.y);
        m.z = fmaxf(m.z, a.z + c.z);
        m.w = fmaxf(m.w, a.w + c.w);
    }
    *reinterpret_cast<float4*>(out + (size_t)n * OUTLD + out_off + f4 * 4) = m;

    __half2 h01, h23;
    h01.x = __float2half_rn(m.x); h01.y = __float2half_rn(m.y);
    h23.x = __float2half_rn(m.z); h23.y = __float2half_rn(m.w);
    *reinterpret_cast<__half2*>(Xh + (size_t)n * LDIM + f4 * 4)     = h01;
    *reinterpret_cast<__half2*>(Xh + (size_t)n * LDIM + f4 * 4 + 2) = h23;
}

// ---------------------------------------------------------------------------
extern "C" void kernel_launch(void* const* d_in, const int* in_sizes, int n_in,
                              void* d_out, int out_size)
{
    const float* rois   = (const float*)d_in[0];
    const float* pooled = (const float*)d_in[1];
    const int*   edge   = (const int*)  d_in[2];   // (2, 65536): row 0 = src
    const float* gW1    = (const float*)d_in[3];
    const float* gb1    = (const float*)d_in[4];
    const float* gW2    = (const float*)d_in[5];
    const float* gb2    = (const float*)d_in[6];
    const float* fcW[3] = {(const float*)d_in[7], (const float*)d_in[9],  (const float*)d_in[11]};
    const float* fcb[3] = {(const float*)d_in[8], (const float*)d_in[10], (const float*)d_in[12]};
    float* out = (float*)d_out;

    const int* src = edge;

    float *H, *D, *biasL;
    __half *X0h, *Xh, *Wh, *Wl;
    cudaGetSymbolAddress((void**)&H,     g_H);
    cudaGetSymbolAddress((void**)&D,     g_D);
    cudaGetSymbolAddress((void**)&biasL, g_biasL);
    cudaGetSymbolAddress((void**)&X0h,   g_X0h);
    cudaGetSymbolAddress((void**)&Xh,    g_Xh);
    cudaGetSymbolAddress((void**)&Wh,    g_Wh);
    cudaGetSymbolAddress((void**)&Wl,    g_Wl);

    cudaFuncSetAttribute(gemm_mma, cudaFuncAttributeMaxDynamicSharedMemorySize, GEMM_SMEM);

    // 1) all weight prep (independent of activations)
    prep_w3<<<dim3(1024, 3), 256>>>(
        fcW[0], fcb[0], fcW[1], fcb[1], fcW[2], fcb[2], Wh, Wl, biasL);

    // 2) geo MLP layer 1: H = relu(rois @ gW1.T + gb1)
    sgemm_tn<<<dim3(GDIM / TN, NNODES / TM), dim3(16, 16)>>>(
        rois, 7, gW1, 7, gb1, H, GDIM, 0, NNODES, GDIM, 7, 1);

    // 3) geo MLP layer 2: out[:,256:384] = relu(H @ gW2.T + gb2)
    sgemm_f2<<<dim3(GDIM / BN, NNODES / BM), 256>>>(
        H, GDIM, gW2, GDIM, gb2, out, OUTLD, CPOOL, GDIM, 1);

    // 4) finish prologue: out[:,0:256] = pooled; X0h = fp16(out[:,0:384])
    finish_pre<<<(NNODES * INDIM + 255) / 256, 256>>>(pooled, out, X0h);

    // 5) three EdgeConv layers
    const int Kin[3]    = {INDIM, LDIM, LDIM};
    const int outOff[3] = {384, 384 + 512, 384 + 1024};

    for (int l = 0; l < 3; l++) {
        const __half* Ain = (l == 0) ? X0h : Xh;
        gemm_mma<<<dim3(1024 / 128, NNODES / 128), 256, GEMM_SMEM>>>(
            Ain, Wh + (size_t)l * WSTRIDE, Wl + (size_t)l * WSTRIDE,
            biasL + l * 1024, D, Kin[l]);

        aggregate<<<NNODES, 128>>>(D, src, Xh, out, outOff[l]);
    }
}

// round 9
// speedup vs baseline: 1.6486x; 1.0318x over previous
#include <cuda_runtime.h>
#include <cuda_bf16.h>
#include <cuda_fp16.h>
#include <cstdint>

// Problem constants
#define NNODES 4096       // B*N = 8*512
#define KNBR   16
#define CPOOL  256
#define GDIM   128
#define INDIM  384        // CPOOL + GDIM
#define LDIM   512
#define OUTLD  1920       // 384 + 3*512
#define WSTRIDE (1024 * 512)

// ---------------- device scratch (no allocations allowed) ----------------
__device__ float g_H   [NNODES * GDIM];
__device__ float g_biasL[3 * 1024];
__device__ __align__(16) __half g_D  [NNODES * 1024];
__device__ __align__(16) __half g_X0h[NNODES * INDIM];
__device__ __align__(16) __half g_Xh [NNODES * LDIM];
__device__ __align__(16) __half g_Wh [3 * WSTRIDE];
__device__ __align__(16) __half g_Wl [3 * WSTRIDE];

// ======================= helpers =======================
__device__ __forceinline__ uint32_t smem_u32(const void* p) {
    uint32_t a;
    asm("{ .reg .u64 t; cvta.to.shared.u64 t, %1; cvt.u32.u64 %0, t; }"
        : "=r"(a) : "l"(p));
    return a;
}
__device__ __forceinline__ uint32_t sw64(uint32_t o) {   // SW64 swizzle for 64B rows
    return o ^ ((o >> 3) & 0x30);
}
__device__ __forceinline__ void cp16(uint32_t dst, const void* src) {
    asm volatile("cp.async.cg.shared.global [%0], [%1], 16;" :: "r"(dst), "l"(src));
}
#define CP_COMMIT() asm volatile("cp.async.commit_group;" ::: "memory")
#define CP_WAIT(n)  asm volatile("cp.async.wait_group %0;" :: "n"(n) : "memory")

#define LDSM4(r, a) \
    asm volatile("ldmatrix.sync.aligned.m8n8.x4.shared.b16 {%0,%1,%2,%3}, [%4];" \
        : "=r"((r)[0]), "=r"((r)[1]), "=r"((r)[2]), "=r"((r)[3]) : "r"(a))

#define MMAF16(d, a, b0, b1) \
    asm volatile("mma.sync.aligned.m16n8k16.row.col.f32.f16.f16.f32 " \
        "{%0,%1,%2,%3}, {%4,%5,%6,%7}, {%8,%9}, {%0,%1,%2,%3};" \
        : "+f"((d)[0]), "+f"((d)[1]), "+f"((d)[2]), "+f"((d)[3]) \
        : "r"((a)[0]), "r"((a)[1]), "r"((a)[2]), "r"((a)[3]), "r"(b0), "r"(b1))

// ======================= mma.sync GEMM (fp16, 2-pass) ======================
// D(4096 x 1024, fp16) = X(4096 x Kin) @ W(1024 x Kin)^T + bias
// A = activations rounded to fp16; W split into fp16 hi + lo (exact).
// D = A*Wh + A*Wl, fp32 accumulation, fp16 store.
// CTA tile 128x128, BK=32, 8 warps (warp tile 32x64), cp.async double buffer.
#define ARR_BYTES (128 * 64)                // 8192
#define STG_BYTES (3 * ARR_BYTES)           // 24576
#define GEMM_SMEM (2 * STG_BYTES)           // 49152

__global__ __launch_bounds__(256) void gemm_mma(
    const __half* __restrict__ A,
    const __half* __restrict__ Bh, const __half* __restrict__ Bl,
    const float* __restrict__ bias,
    __half* __restrict__ C,     // ldc = 1024, fp16
    int Kin)
{
    extern __shared__ char smem[];
    const uint32_t sb  = smem_u32(smem);
    const int tid  = threadIdx.x;
    const int lane = tid & 31;
    const int wid  = tid >> 5;
    const int bm   = blockIdx.y * 128;
    const int bn   = blockIdx.x * 128;
    const int m0   = (wid & 3) * 32;     // warp m-offset in tile
    const int n0   = (wid >> 2) * 64;    // warp n-offset in tile

    // cp.async chunk mapping: 512 chunks of 16B per array, 2 per thread
    const int r0c = tid >> 2;            // rows 0..63
    const int s0c = tid & 3;             // seg 0..3
    const int r1c = (tid + 256) >> 2;    // rows 64..127

    const __half* gsrc[3] = { A, Bh, Bl };
    const int grow0[3] = { bm, bn, bn };

    uint32_t soff0[3], soff1[3];
    #pragma unroll
    for (int a = 0; a < 3; a++) {
        soff0[a] = a * ARR_BYTES + sw64((uint32_t)(r0c * 64 + s0c * 16));
        soff1[a] = a * ARR_BYTES + sw64((uint32_t)(r1c * 64 + s0c * 16));
    }

    const int nk = Kin / 32;

    // ---- issue stage 0 ----
    {
        const uint32_t bufb = sb;
        #pragma unroll
        for (int a = 0; a < 3; a++) {
            cp16(bufb + soff0[a], gsrc[a] + (size_t)(grow0[a] + r0c) * Kin + s0c * 8);
            cp16(bufb + soff1[a], gsrc[a] + (size_t)(grow0[a] + r1c) * Kin + s0c * 8);
        }
        CP_COMMIT();
    }

    float acc[2][8][4];
    #pragma unroll
    for (int i = 0; i < 2; i++)
        #pragma unroll
        for (int j = 0; j < 8; j++)
            #pragma unroll
            for (int q = 0; q < 4; q++)
                acc[i][j][q] = 0.0f;

    // ldmatrix per-lane address components
    const int a_row = lane & 15;
    const int a_kh  = (lane >> 4) & 1;
    const int b_row = ((lane >> 4) << 3) + (lane & 7);
    const int b_kh  = (lane >> 3) & 1;

    for (int s = 0; s < nk; s++) {
        const uint32_t bufb = sb + (uint32_t)(s & 1) * STG_BYTES;

        if (s + 1 < nk) {
            const uint32_t nb = sb + (uint32_t)((s + 1) & 1) * STG_BYTES;
            const int kb = (s + 1) * 32;
            #pragma unroll
            for (int a = 0; a < 3; a++) {
                cp16(nb + soff0[a], gsrc[a] + (size_t)(grow0[a] + r0c) * Kin + kb + s0c * 8);
                cp16(nb + soff1[a], gsrc[a] + (size_t)(grow0[a] + r1c) * Kin + kb + s0c * 8);
            }
            CP_COMMIT();
            CP_WAIT(1);
        } else {
            CP_WAIT(0);
        }
        __syncthreads();

        #pragma unroll
        for (int kk = 0; kk < 2; kk++) {
            uint32_t fa[2][4];
            #pragma unroll
            for (int mt = 0; mt < 2; mt++) {
                const uint32_t off =
                    sw64((uint32_t)((m0 + mt * 16 + a_row) * 64 + kk * 32 + a_kh * 16));
                LDSM4(fa[mt], bufb + 0 * ARR_BYTES + off);
            }
            uint32_t fbh[4][4], fbl[4][4];
            #pragma unroll
            for (int nt = 0; nt < 4; nt++) {
                const uint32_t off =
                    sw64((uint32_t)((n0 + nt * 16 + b_row) * 64 + kk * 32 + b_kh * 16));
                LDSM4(fbh[nt], bufb + 1 * ARR_BYTES + off);
                LDSM4(fbl[nt], bufb + 2 * ARR_BYTES + off);
            }
            #pragma unroll
            for (int mt = 0; mt < 2; mt++) {
                #pragma unroll
                for (int ni = 0; ni < 8; ni++) {
                    const uint32_t bh0 = fbh[ni >> 1][(ni & 1) * 2];
                    const uint32_t bh1 = fbh[ni >> 1][(ni & 1) * 2 + 1];
                    const uint32_t bl0 = fbl[ni >> 1][(ni & 1) * 2];
                    const uint32_t bl1 = fbl[ni >> 1][(ni & 1) * 2 + 1];
                    MMAF16(acc[mt][ni], fa[mt], bh0, bh1);
                    MMAF16(acc[mt][ni], fa[mt], bl0, bl1);
                }
            }
        }
        __syncthreads();
    }

    // ---- epilogue: write D (fp16) with bias ----
    #pragma unroll
    for (int mt = 0; mt < 2; mt++) {
        const int r = bm + m0 + mt * 16 + (lane >> 2);
        #pragma unroll
        for (int ni = 0; ni < 8; ni++) {
            const int col = bn + n0 + ni * 8 + (lane & 3) * 2;
            const float b0 = bias[col], b1 = bias[col + 1];
            __half2 v0 = __floats2half2_rn(acc[mt][ni][0] + b0, acc[mt][ni][1] + b1);
            __half2 v1 = __floats2half2_rn(acc[mt][ni][2] + b0, acc[mt][ni][3] + b1);
            *(__half2*)(C + (size_t)r * 1024 + col)       = v0;
            *(__half2*)(C + (size_t)(r + 8) * 1024 + col) = v1;
        }
    }
}

// ---------------- generic tiled SGEMM (K=7 geo layer) ------
#define TM 64
#define TN 64
#define TK 16

__global__ void sgemm_tn(const float* __restrict__ A, int lda,
                         const float* __restrict__ B, int ldb,
                         const float* __restrict__ bias,
                         float* __restrict__ C, int ldc, int c_off,
                         int M, int N, int K, int do_relu)
{
    __shared__ float Ams[TK][TM];
    __shared__ float Bms[TK][TN];

    const int bm = blockIdx.y * TM;
    const int bn = blockIdx.x * TN;
    const int tx = threadIdx.x;
    const int ty = threadIdx.y;
    const int tid = ty * 16 + tx;

    float acc[4][4] = {};

    for (int k0 = 0; k0 < K; k0 += TK) {
        #pragma unroll
        for (int i = tid; i < TM * TK; i += 256) {
            int m = i / TK, k = i % TK;
            float v = 0.0f;
            int gm = bm + m, gk = k0 + k;
            if (gm < M && gk < K) v = A[(size_t)gm * lda + gk];
            Ams[k][m] = v;
        }
        #pragma unroll
        for (int i = tid; i < TN * TK; i += 256) {
            int n = i / TK, k = i % TK;
            float v = 0.0f;
            int gn = bn + n, gk = k0 + k;
            if (gn < N && gk < K) v = B[(size_t)gn * ldb + gk];
            Bms[k][n] = v;
        }
        __syncthreads();

        #pragma unroll
        for (int kk = 0; kk < TK; kk++) {
            float4 av = *reinterpret_cast<const float4*>(&Ams[kk][ty * 4]);
            float4 bv = *reinterpret_cast<const float4*>(&Bms[kk][tx * 4]);
            float a[4] = {av.x, av.y, av.z, av.w};
            float b[4] = {bv.x, bv.y, bv.z, bv.w};
            #pragma unroll
            for (int i = 0; i < 4; i++)
                #pragma unroll
                for (int j = 0; j < 4; j++)
                    acc[i][j] = fmaf(a[i], b[j], acc[i][j]);
        }
        __syncthreads();
    }

    #pragma unroll
    for (int i = 0; i < 4; i++) {
        int m = bm + ty * 4 + i;
        if (m >= M) continue;
        #pragma unroll
        for (int j = 0; j < 4; j++) {
            int n = bn + tx * 4 + j;
            if (n >= N) continue;
            float v = acc[i][j];
            if (bias) v += bias[n];
            if (do_relu) v = fmaxf(v, 0.0f);
            C[(size_t)m * ldc + c_off + n] = v;
        }
    }
}

// ---------------- f32x2 SGEMM (geo layer 2, K=128) ----------------
#define BM 128
#define BN 64
#define BK 16

__global__ __launch_bounds__(256) void sgemm_f2(
    const float* __restrict__ A, int lda,
    const float* __restrict__ B, int ldb,
    const float* __restrict__ bias,
    float* __restrict__ C, int ldc, int c_off,
    int K, int do_relu)
{
    __shared__ float As[2][BK][BM];
    __shared__ float Bs[2][BK][BN];

    const int tid = threadIdx.x;
    const int tx  = tid & 15;
    const int ty  = tid >> 4;
    const int bm  = blockIdx.y * BM;
    const int bn  = blockIdx.x * BN;

    const int am  = tid >> 1;
    const int ak  = (tid & 1) * 8;
    const int bnr = tid >> 2;
    const int bk  = (tid & 3) * 4;

    const float* Aptr = A + (size_t)(bm + am) * lda + ak;
    const float* Bptr = B + (size_t)(bn + bnr) * ldb + bk;

    float4 ra0 = *(const float4*)(Aptr);
    float4 ra1 = *(const float4*)(Aptr + 4);
    float4 rb  = *(const float4*)(Bptr);

    As[0][ak + 0][am] = ra0.x;  As[0][ak + 1][am] = ra0.y;
    As[0][ak + 2][am] = ra0.z;  As[0][ak + 3][am] = ra0.w;
    As[0][ak + 4][am] = ra1.x;  As[0][ak + 5][am] = ra1.y;
    As[0][ak + 6][am] = ra1.z;  As[0][ak + 7][am] = ra1.w;
    Bs[0][bk + 0][bnr] = rb.x;  Bs[0][bk + 1][bnr] = rb.y;
    Bs[0][bk + 2][bnr] = rb.z;  Bs[0][bk + 3][bnr] = rb.w;

    unsigned long long acc[4][4];
    #pragma unroll
    for (int i = 0; i < 4; i++)
        #pragma unroll
        for (int j = 0; j < 4; j++)
            acc[i][j] = 0ull;

    const int nk = K / BK;
    int buf = 0;
    __syncthreads();

    for (int kt = 0; kt < nk; kt++) {
        const bool has_next = (kt + 1 < nk);
        if (has_next) {
            const float* Ap = Aptr + (kt + 1) * BK;
            ra0 = *(const float4*)(Ap);
            ra1 = *(const float4*)(Ap + 4);
            rb  = *(const float4*)(Bptr + (kt + 1) * BK);
        }

        #pragma unroll
        for (int kk = 0; kk < BK; kk++) {
            ulonglong2 av0 = *(const ulonglong2*)&As[buf][kk][ty * 8];
            ulonglong2 av1 = *(const ulonglong2*)&As[buf][kk][ty * 8 + 4];
            unsigned long long a0 = av0.x, a1 = av0.y, a2 = av1.x, a3 = av1.y;

            float4 bq = *(const float4*)&Bs[buf][kk][tx * 4];
            unsigned long long b0, b1, b2, b3;
            asm("mov.b64 %0, {%1, %1};" : "=l"(b0) : "f"(bq.x));
            asm("mov.b64 %0, {%1, %1};" : "=l"(b1) : "f"(bq.y));
            asm("mov.b64 %0, {%1, %1};" : "=l"(b2) : "f"(bq.z));
            asm("mov.b64 %0, {%1, %1};" : "=l"(b3) : "f"(bq.w));

            #define FF2(d, a, b) \
                asm("fma.rn.f32x2 %0, %1, %2, %0;" : "+l"(d) : "l"(a), "l"(b))
            FF2(acc[0][0], a0, b0); FF2(acc[0][1], a0, b1);
            FF2(acc[0][2], a0, b2); FF2(acc[0][3], a0, b3);
            FF2(acc[1][0], a1, b0); FF2(acc[1][1], a1, b1);
            FF2(acc[1][2], a1, b2); FF2(acc[1][3], a1, b3);
            FF2(acc[2][0], a2, b0); FF2(acc[2][1], a2, b1);
            FF2(acc[2][2], a2, b2); FF2(acc[2][3], a2, b3);
            FF2(acc[3][0], a3, b0); FF2(acc[3][1], a3, b1);
            FF2(acc[3][2], a3, b2); FF2(acc[3][3], a3, b3);
            #undef FF2
        }

        if (has_next) {
            const int nb = buf ^ 1;
            As[nb][ak + 0][am] = ra0.x;  As[nb][ak + 1][am] = ra0.y;
            As[nb][ak + 2][am] = ra0.z;  As[nb][ak + 3][am] = ra0.w;
            As[nb][ak + 4][am] = ra1.x;  As[nb][ak + 5][am] = ra1.y;
            As[nb][ak + 6][am] = ra1.z;  As[nb][ak + 7][am] = ra1.w;
            Bs[nb][bk + 0][bnr] = rb.x;  Bs[nb][bk + 1][bnr] = rb.y;
            Bs[nb][bk + 2][bnr] = rb.z;  Bs[nb][bk + 3][bnr] = rb.w;
            __syncthreads();
            buf = nb;
        }
    }

    #pragma unroll
    for (int mp = 0; mp < 4; mp++) {
        const int r0 = bm + ty * 8 + mp * 2;
        #pragma unroll
        for (int j = 0; j < 4; j++) {
            const int n = bn + tx * 4 + j;
            float lo, hi;
            asm("mov.b64 {%0, %1}, %2;" : "=f"(lo), "=f"(hi) : "l"(acc[mp][j]));
            float bv = bias ? bias[n] : 0.0f;
            lo += bv; hi += bv;
            if (do_relu) { lo = fmaxf(lo, 0.0f); hi = fmaxf(hi, 0.0f); }
            C[(size_t)r0 * ldc + c_off + n]       = lo;
            C[(size_t)(r0 + 1) * ldc + c_off + n] = hi;
        }
    }
}

// ======================= weight prep (all 3 layers, fp16 hi/lo) ============
__global__ void prep_w3(
    const float* __restrict__ W0, const float* __restrict__ b0,
    const float* __restrict__ W1, const float* __restrict__ b1,
    const float* __restrict__ W2, const float* __restrict__ b2,
    __half* __restrict__ Wh, __half* __restrict__ Wl,
    float* __restrict__ biasL)
{
    const int layer = blockIdx.y;
    const float* W = (layer == 0) ? W0 : (layer == 1) ? W1 : W2;
    const float* b = (layer == 0) ? b0 : (layer == 1) ? b1 : b2;
    const int Kin  = (layer == 0) ? INDIM : LDIM;

    __half* wh = Wh + (size_t)layer * WSTRIDE;
    __half* wl = Wl + (size_t)layer * WSTRIDE;

    int idx = blockIdx.x * blockDim.x + threadIdx.x;
    if (idx < 512 * Kin) {
        int r = idx / Kin, c = idx % Kin;
        float vl = W[(size_t)r * 2 * Kin + c];
        float vr = W[(size_t)r * 2 * Kin + Kin + c];
        float d  = vr - vl;

        __half h = __float2half_rn(vl);
        wh[(size_t)r * Kin + c] = h;
        wl[(size_t)r * Kin + c] = __float2half_rn(vl - __half2float(h));
        h = __float2half_rn(d);
        wh[(size_t)(512 + r) * Kin + c] = h;
        wl[(size_t)(512 + r) * Kin + c] = __float2half_rn(d - __half2float(h));
    }
    if (idx < 512) {
        biasL[layer * 1024 + idx]       = 0.0f;
        biasL[layer * 1024 + 512 + idx] = b[idx];
    }
}

// ------------- finish prologue: pooled copy + fp16 convert of X0 ----------
// Requires out[:,256:384] already written by sgemm_f2.
__global__ void finish_pre(const float* __restrict__ pooled,
                           float* __restrict__ out,
                           __half* __restrict__ X0h)
{
    int idx = blockIdx.x * blockDim.x + threadIdx.x;
    if (idx >= NNODES * INDIM) return;
    int n = idx / INDIM;
    int c = idx - n * INDIM;
    float v;
    if (c < CPOOL) {
        v = pooled[(size_t)n * CPOOL + c];
        out[(size_t)n * OUTLD + c] = v;
    } else {
        v = out[(size_t)n * OUTLD + c];
    }
    X0h[idx] = __float2half_rn(v);
}

// ---------------- aggregation (fp16 D) + fp16 convert of new features -----
__global__ __launch_bounds__(128) void aggregate(
    const __half* __restrict__ D,
    const int*   __restrict__ src,
    __half* __restrict__ Xh,         // 4096 x 512
    float* __restrict__ out,         // 4096 x 1920
    int out_off)
{
    const int n  = blockIdx.x;
    const int f4 = threadIdx.x;   // 0..127, covers 4 halves (8B) each

    uint2 cw = *(const uint2*)(D + (size_t)n * 1024 + 512 + f4 * 4);
    float2 c01 = __half22float2(*(__half2*)&cw.x);
    float2 c23 = __half22float2(*(__half2*)&cw.y);
    float4 m = make_float4(0.f, 0.f, 0.f, 0.f);

    #pragma unroll
    for (int k = 0; k < KNBR; k++) {
        int j = src[n * KNBR + k];
        uint2 aw = *(const uint2*)(D + (size_t)j * 1024 + f4 * 4);
        float2 a01 = __half22float2(*(__half2*)&aw.x);
        float2 a23 = __half22float2(*(__half2*)&aw.y);
        m.x = fmaxf(m.x, a01.x + c01.x);
        m.y = fmaxf(m.y, a01.y + c01.y);
        m.z = fmaxf(m.z, a23.x + c23.x);
        m.w = fmaxf(m.w, a23.y + c23.y);
    }
    *reinterpret_cast<float4*>(out + (size_t)n * OUTLD + out_off + f4 * 4) = m;

    __half2 h01 = __floats2half2_rn(m.x, m.y);
    __half2 h23 = __floats2half2_rn(m.z, m.w);
    *reinterpret_cast<__half2*>(Xh + (size_t)n * LDIM + f4 * 4)     = h01;
    *reinterpret_cast<__half2*>(Xh + (size_t)n * LDIM + f4 * 4 + 2) = h23;
}

// ---------------------------------------------------------------------------
extern "C" void kernel_launch(void* const* d_in, const int* in_sizes, int n_in,
                              void* d_out, int out_size)
{
    const float* rois   = (const float*)d_in[0];
    const float* pooled = (const float*)d_in[1];
    const int*   edge   = (const int*)  d_in[2];   // (2, 65536): row 0 = src
    const float* gW1    = (const float*)d_in[3];
    const float* gb1    = (const float*)d_in[4];
    const float* gW2    = (const float*)d_in[5];
    const float* gb2    = (const float*)d_in[6];
    const float* fcW[3] = {(const float*)d_in[7], (const float*)d_in[9],  (const float*)d_in[11]};
    const float* fcb[3] = {(const float*)d_in[8], (const float*)d_in[10], (const float*)d_in[12]};
    float* out = (float*)d_out;

    const int* src = edge;

    float *H, *biasL;
    __half *D, *X0h, *Xh, *Wh, *Wl;
    cudaGetSymbolAddress((void**)&H,     g_H);
    cudaGetSymbolAddress((void**)&D,     g_D);
    cudaGetSymbolAddress((void**)&biasL, g_biasL);
    cudaGetSymbolAddress((void**)&X0h,   g_X0h);
    cudaGetSymbolAddress((void**)&Xh,    g_Xh);
    cudaGetSymbolAddress((void**)&Wh,    g_Wh);
    cudaGetSymbolAddress((void**)&Wl,    g_Wl);

    cudaFuncSetAttribute(gemm_mma, cudaFuncAttributeMaxDynamicSharedMemorySize, GEMM_SMEM);

    // 1) all weight prep (independent of activations)
    prep_w3<<<dim3(1024, 3), 256>>>(
        fcW[0], fcb[0], fcW[1], fcb[1], fcW[2], fcb[2], Wh, Wl, biasL);

    // 2) geo MLP layer 1: H = relu(rois @ gW1.T + gb1)
    sgemm_tn<<<dim3(GDIM / TN, NNODES / TM), dim3(16, 16)>>>(
        rois, 7, gW1, 7, gb1, H, GDIM, 0, NNODES, GDIM, 7, 1);

    // 3) geo MLP layer 2: out[:,256:384] = relu(H @ gW2.T + gb2)
    sgemm_f2<<<dim3(GDIM / BN, NNODES / BM), 256>>>(
        H, GDIM, gW2, GDIM, gb2, out, OUTLD, CPOOL, GDIM, 1);

    // 4) finish prologue: out[:,0:256] = pooled; X0h = fp16(out[:,0:384])
    finish_pre<<<(NNODES * INDIM + 255) / 256, 256>>>(pooled, out, X0h);

    // 5) three EdgeConv layers
    const int Kin[3]    = {INDIM, LDIM, LDIM};
    const int outOff[3] = {384, 384 + 512, 384 + 1024};

    for (int l = 0; l < 3; l++) {
        const __half* Ain = (l == 0) ? X0h : Xh;
        gemm_mma<<<dim3(1024 / 128, NNODES / 128), 256, GEMM_SMEM>>>(
            Ain, Wh + (size_t)l * WSTRIDE, Wl + (size_t)l * WSTRIDE,
            biasL + l * 1024, D, Kin[l]);

        aggregate<<<NNODES, 128>>>(D, src, Xh, out, outOff[l]);
    }
}

// round 11
// speedup vs baseline: 1.6802x; 1.0191x over previous
#include <cuda_runtime.h>
#include <cuda_bf16.h>
#include <cuda_fp16.h>
#include <cstdint>

// Problem constants
#define NNODES 4096       // B*N = 8*512
#define KNBR   16
#define CPOOL  256
#define GDIM   128
#define INDIM  384        // CPOOL + GDIM
#define LDIM   512
#define OUTLD  1920       // 384 + 3*512
#define WSTRIDE (1024 * 512)

// ---------------- device scratch (no allocations allowed) ----------------
__device__ float g_H   [NNODES * GDIM];
__device__ float g_biasL[3 * 1024];
__device__ __align__(16) __half g_D  [NNODES * 1024];
__device__ __align__(16) __half g_X0h[NNODES * INDIM];
__device__ __align__(16) __half g_Xh [NNODES * LDIM];
__device__ __align__(16) __half g_Wh [3 * WSTRIDE];
__device__ __align__(16) __half g_Wl [3 * WSTRIDE];

// ======================= helpers =======================
__device__ __forceinline__ uint32_t smem_u32(const void* p) {
    uint32_t a;
    asm("{ .reg .u64 t; cvta.to.shared.u64 t, %1; cvt.u32.u64 %0, t; }"
        : "=r"(a) : "l"(p));
    return a;
}
__device__ __forceinline__ uint32_t sw64(uint32_t o) {   // SW64 swizzle for 64B rows
    return o ^ ((o >> 3) & 0x30);
}
__device__ __forceinline__ void cp16(uint32_t dst, const void* src) {
    asm volatile("cp.async.cg.shared.global [%0], [%1], 16;" :: "r"(dst), "l"(src));
}
#define CP_COMMIT() asm volatile("cp.async.commit_group;" ::: "memory")
#define CP_WAIT(n)  asm volatile("cp.async.wait_group %0;" :: "n"(n) : "memory")

#define LDSM4(r, a) \
    asm volatile("ldmatrix.sync.aligned.m8n8.x4.shared.b16 {%0,%1,%2,%3}, [%4];" \
        : "=r"((r)[0]), "=r"((r)[1]), "=r"((r)[2]), "=r"((r)[3]) : "r"(a))

#define MMAF16(d, a, b0, b1) \
    asm volatile("mma.sync.aligned.m16n8k16.row.col.f32.f16.f16.f32 " \
        "{%0,%1,%2,%3}, {%4,%5,%6,%7}, {%8,%9}, {%0,%1,%2,%3};" \
        : "+f"((d)[0]), "+f"((d)[1]), "+f"((d)[2]), "+f"((d)[3]) \
        : "r"((a)[0]), "r"((a)[1]), "r"((a)[2]), "r"((a)[3]), "r"(b0), "r"(b1))

// ======================= mma.sync GEMM (fp16, 2-pass) ======================
// D(4096 x 1024, fp16) = X(4096 x Kin) @ W(1024 x Kin)^T + bias
// A = activations rounded to fp16; W split into fp16 hi + lo (exact).
// D = A*Wh + A*Wl, fp32 accumulation, fp16 store.
// CTA tile 128x128, BK=32, 8 warps (warp tile 32x64), cp.async double buffer.
#define ARR_BYTES (128 * 64)                // 8192
#define STG_BYTES (3 * ARR_BYTES)           // 24576
#define GEMM_SMEM (2 * STG_BYTES)           // 49152

__global__ __launch_bounds__(256) void gemm_mma(
    const __half* __restrict__ A,
    const __half* __restrict__ Bh, const __half* __restrict__ Bl,
    const float* __restrict__ bias,
    __half* __restrict__ C,     // ldc = 1024, fp16
    int Kin)
{
    extern __shared__ char smem[];
    const uint32_t sb  = smem_u32(smem);
    const int tid  = threadIdx.x;
    const int lane = tid & 31;
    const int wid  = tid >> 5;
    const int bm   = blockIdx.y * 128;
    const int bn   = blockIdx.x * 128;
    const int m0   = (wid & 3) * 32;     // warp m-offset in tile
    const int n0   = (wid >> 2) * 64;    // warp n-offset in tile

    // cp.async chunk mapping: 512 chunks of 16B per array, 2 per thread
    const int r0c = tid >> 2;            // rows 0..63
    const int s0c = tid & 3;             // seg 0..3
    const int r1c = (tid + 256) >> 2;    // rows 64..127

    const __half* gsrc[3] = { A, Bh, Bl };
    const int grow0[3] = { bm, bn, bn };

    uint32_t soff0[3], soff1[3];
    #pragma unroll
    for (int a = 0; a < 3; a++) {
        soff0[a] = a * ARR_BYTES + sw64((uint32_t)(r0c * 64 + s0c * 16));
        soff1[a] = a * ARR_BYTES + sw64((uint32_t)(r1c * 64 + s0c * 16));
    }

    const int nk = Kin / 32;

    // ---- issue stage 0 ----
    {
        const uint32_t bufb = sb;
        #pragma unroll
        for (int a = 0; a < 3; a++) {
            cp16(bufb + soff0[a], gsrc[a] + (size_t)(grow0[a] + r0c) * Kin + s0c * 8);
            cp16(bufb + soff1[a], gsrc[a] + (size_t)(grow0[a] + r1c) * Kin + s0c * 8);
        }
        CP_COMMIT();
    }

    float acc[2][8][4];
    #pragma unroll
    for (int i = 0; i < 2; i++)
        #pragma unroll
        for (int j = 0; j < 8; j++)
            #pragma unroll
            for (int q = 0; q < 4; q++)
                acc[i][j][q] = 0.0f;

    // ldmatrix per-lane address components
    const int a_row = lane & 15;
    const int a_kh  = (lane >> 4) & 1;
    const int b_row = ((lane >> 4) << 3) + (lane & 7);
    const int b_kh  = (lane >> 3) & 1;

    for (int s = 0; s < nk; s++) {
        const uint32_t bufb = sb + (uint32_t)(s & 1) * STG_BYTES;

        if (s + 1 < nk) {
            const uint32_t nb = sb + (uint32_t)((s + 1) & 1) * STG_BYTES;
            const int kb = (s + 1) * 32;
            #pragma unroll
            for (int a = 0; a < 3; a++) {
                cp16(nb + soff0[a], gsrc[a] + (size_t)(grow0[a] + r0c) * Kin + kb + s0c * 8);
                cp16(nb + soff1[a], gsrc[a] + (size_t)(grow0[a] + r1c) * Kin + kb + s0c * 8);
            }
            CP_COMMIT();
            CP_WAIT(1);
        } else {
            CP_WAIT(0);
        }
        __syncthreads();

        #pragma unroll
        for (int kk = 0; kk < 2; kk++) {
            uint32_t fa[2][4];
            #pragma unroll
            for (int mt = 0; mt < 2; mt++) {
                const uint32_t off =
                    sw64((uint32_t)((m0 + mt * 16 + a_row) * 64 + kk * 32 + a_kh * 16));
                LDSM4(fa[mt], bufb + 0 * ARR_BYTES + off);
            }
            uint32_t fbh[4][4], fbl[4][4];
            #pragma unroll
            for (int nt = 0; nt < 4; nt++) {
                const uint32_t off =
                    sw64((uint32_t)((n0 + nt * 16 + b_row) * 64 + kk * 32 + b_kh * 16));
                LDSM4(fbh[nt], bufb + 1 * ARR_BYTES + off);
                LDSM4(fbl[nt], bufb + 2 * ARR_BYTES + off);
            }
            #pragma unroll
            for (int mt = 0; mt < 2; mt++) {
                #pragma unroll
                for (int ni = 0; ni < 8; ni++) {
                    const uint32_t bh0 = fbh[ni >> 1][(ni & 1) * 2];
                    const uint32_t bh1 = fbh[ni >> 1][(ni & 1) * 2 + 1];
                    const uint32_t bl0 = fbl[ni >> 1][(ni & 1) * 2];
                    const uint32_t bl1 = fbl[ni >> 1][(ni & 1) * 2 + 1];
                    MMAF16(acc[mt][ni], fa[mt], bh0, bh1);
                    MMAF16(acc[mt][ni], fa[mt], bl0, bl1);
                }
            }
        }
        __syncthreads();
    }

    // ---- epilogue: write D (fp16) with bias ----
    #pragma unroll
    for (int mt = 0; mt < 2; mt++) {
        const int r = bm + m0 + mt * 16 + (lane >> 2);
        #pragma unroll
        for (int ni = 0; ni < 8; ni++) {
            const int col = bn + n0 + ni * 8 + (lane & 3) * 2;
            const float b0 = bias[col], b1 = bias[col + 1];
            __half2 v0 = __floats2half2_rn(acc[mt][ni][0] + b0, acc[mt][ni][1] + b1);
            __half2 v1 = __floats2half2_rn(acc[mt][ni][2] + b0, acc[mt][ni][3] + b1);
            *(__half2*)(C + (size_t)r * 1024 + col)       = v0;
            *(__half2*)(C + (size_t)(r + 8) * 1024 + col) = v1;
        }
    }
}

// ---------------- generic tiled SGEMM (K=7 geo layer) ------
#define TM 64
#define TN 64
#define TK 16

__global__ void sgemm_tn(const float* __restrict__ A, int lda,
                         const float* __restrict__ B, int ldb,
                         const float* __restrict__ bias,
                         float* __restrict__ C, int ldc, int c_off,
                         int M, int N, int K, int do_relu)
{
    __shared__ float Ams[TK][TM];
    __shared__ float Bms[TK][TN];

    const int bm = blockIdx.y * TM;
    const int bn = blockIdx.x * TN;
    const int tx = threadIdx.x;
    const int ty = threadIdx.y;
    const int tid = ty * 16 + tx;

    float acc[4][4] = {};

    for (int k0 = 0; k0 < K; k0 += TK) {
        #pragma unroll
        for (int i = tid; i < TM * TK; i += 256) {
            int m = i / TK, k = i % TK;
            float v = 0.0f;
            int gm = bm + m, gk = k0 + k;
            if (gm < M && gk < K) v = A[(size_t)gm * lda + gk];
            Ams[k][m] = v;
        }
        #pragma unroll
        for (int i = tid; i < TN * TK; i += 256) {
            int n = i / TK, k = i % TK;
            float v = 0.0f;
            int gn = bn + n, gk = k0 + k;
            if (gn < N && gk < K) v = B[(size_t)gn * ldb + gk];
            Bms[k][n] = v;
        }
        __syncthreads();

        #pragma unroll
        for (int kk = 0; kk < TK; kk++) {
            float4 av = *reinterpret_cast<const float4*>(&Ams[kk][ty * 4]);
            float4 bv = *reinterpret_cast<const float4*>(&Bms[kk][tx * 4]);
            float a[4] = {av.x, av.y, av.z, av.w};
            float b[4] = {bv.x, bv.y, bv.z, bv.w};
            #pragma unroll
            for (int i = 0; i < 4; i++)
                #pragma unroll
                for (int j = 0; j < 4; j++)
                    acc[i][j] = fmaf(a[i], b[j], acc[i][j]);
        }
        __syncthreads();
    }

    #pragma unroll
    for (int i = 0; i < 4; i++) {
        int m = bm + ty * 4 + i;
        if (m >= M) continue;
        #pragma unroll
        for (int j = 0; j < 4; j++) {
            int n = bn + tx * 4 + j;
            if (n >= N) continue;
            float v = acc[i][j];
            if (bias) v += bias[n];
            if (do_relu) v = fmaxf(v, 0.0f);
            C[(size_t)m * ldc + c_off + n] = v;
        }
    }
}

// ------- f32x2 SGEMM (geo layer 2, K=128) with fused fp16 epilogue --------
// C fp32 (ldc/c_off) AND Xh fp16 (xld/x_off) both written with relu result.
#define BM 128
#define BN 64
#define BK 16

__global__ __launch_bounds__(256) void sgemm_f2(
    const float* __restrict__ A, int lda,
    const float* __restrict__ B, int ldb,
    const float* __restrict__ bias,
    float* __restrict__ C, int ldc, int c_off,
    __half* __restrict__ Xh, int xld, int x_off,
    int K)
{
    __shared__ float As[2][BK][BM];
    __shared__ float Bs[2][BK][BN];

    const int tid = threadIdx.x;
    const int tx  = tid & 15;
    const int ty  = tid >> 4;
    const int bm  = blockIdx.y * BM;
    const int bn  = blockIdx.x * BN;

    const int am  = tid >> 1;
    const int ak  = (tid & 1) * 8;
    const int bnr = tid >> 2;
    const int bk  = (tid & 3) * 4;

    const float* Aptr = A + (size_t)(bm + am) * lda + ak;
    const float* Bptr = B + (size_t)(bn + bnr) * ldb + bk;

    float4 ra0 = *(const float4*)(Aptr);
    float4 ra1 = *(const float4*)(Aptr + 4);
    float4 rb  = *(const float4*)(Bptr);

    As[0][ak + 0][am] = ra0.x;  As[0][ak + 1][am] = ra0.y;
    As[0][ak + 2][am] = ra0.z;  As[0][ak + 3][am] = ra0.w;
    As[0][ak + 4][am] = ra1.x;  As[0][ak + 5][am] = ra1.y;
    As[0][ak + 6][am] = ra1.z;  As[0][ak + 7][am] = ra1.w;
    Bs[0][bk + 0][bnr] = rb.x;  Bs[0][bk + 1][bnr] = rb.y;
    Bs[0][bk + 2][bnr] = rb.z;  Bs[0][bk + 3][bnr] = rb.w;

    unsigned long long acc[4][4];
    #pragma unroll
    for (int i = 0; i < 4; i++)
        #pragma unroll
        for (int j = 0; j < 4; j++)
            acc[i][j] = 0ull;

    const int nk = K / BK;
    int buf = 0;
    __syncthreads();

    for (int kt = 0; kt < nk; kt++) {
        const bool has_next = (kt + 1 < nk);
        if (has_next) {
            const float* Ap = Aptr + (kt + 1) * BK;
            ra0 = *(const float4*)(Ap);
            ra1 = *(const float4*)(Ap + 4);
            rb  = *(const float4*)(Bptr + (kt + 1) * BK);
        }

        #pragma unroll
        for (int kk = 0; kk < BK; kk++) {
            ulonglong2 av0 = *(const ulonglong2*)&As[buf][kk][ty * 8];
            ulonglong2 av1 = *(const ulonglong2*)&As[buf][kk][ty * 8 + 4];
            unsigned long long a0 = av0.x, a1 = av0.y, a2 = av1.x, a3 = av1.y;

            float4 bq = *(const float4*)&Bs[buf][kk][tx * 4];
            unsigned long long b0, b1, b2, b3;
            asm("mov.b64 %0, {%1, %1};" : "=l"(b0) : "f"(bq.x));
            asm("mov.b64 %0, {%1, %1};" : "=l"(b1) : "f"(bq.y));
            asm("mov.b64 %0, {%1, %1};" : "=l"(b2) : "f"(bq.z));
            asm("mov.b64 %0, {%1, %1};" : "=l"(b3) : "f"(bq.w));

            #define FF2(d, a, b) \
                asm("fma.rn.f32x2 %0, %1, %2, %0;" : "+l"(d) : "l"(a), "l"(b))
            FF2(acc[0][0], a0, b0); FF2(acc[0][1], a0, b1);
            FF2(acc[0][2], a0, b2); FF2(acc[0][3], a0, b3);
            FF2(acc[1][0], a1, b0); FF2(acc[1][1], a1, b1);
            FF2(acc[1][2], a1, b2); FF2(acc[1][3], a1, b3);
            FF2(acc[2][0], a2, b0); FF2(acc[2][1], a2, b1);
            FF2(acc[2][2], a2, b2); FF2(acc[2][3], a2, b3);
            FF2(acc[3][0], a3, b0); FF2(acc[3][1], a3, b1);
            FF2(acc[3][2], a3, b2); FF2(acc[3][3], a3, b3);
            #undef FF2
        }

        if (has_next) {
            const int nb = buf ^ 1;
            As[nb][ak + 0][am] = ra0.x;  As[nb][ak + 1][am] = ra0.y;
            As[nb][ak + 2][am] = ra0.z;  As[nb][ak + 3][am] = ra0.w;
            As[nb][ak + 4][am] = ra1.x;  As[nb][ak + 5][am] = ra1.y;
            As[nb][ak + 6][am] = ra1.z;  As[nb][ak + 7][am] = ra1.w;
            Bs[nb][bk + 0][bnr] = rb.x;  Bs[nb][bk + 1][bnr] = rb.y;
            Bs[nb][bk + 2][bnr] = rb.z;  Bs[nb][bk + 3][bnr] = rb.w;
            __syncthreads();
            buf = nb;
        }
    }

    #pragma unroll
    for (int mp = 0; mp < 4; mp++) {
        const int r0 = bm + ty * 8 + mp * 2;
        #pragma unroll
        for (int j = 0; j < 4; j++) {
            const int n = bn + tx * 4 + j;
            float lo, hi;
            asm("mov.b64 {%0, %1}, %2;" : "=f"(lo), "=f"(hi) : "l"(acc[mp][j]));
            float bv = bias[n];
            lo = fmaxf(lo + bv, 0.0f);
            hi = fmaxf(hi + bv, 0.0f);
            C[(size_t)r0 * ldc + c_off + n]       = lo;
            C[(size_t)(r0 + 1) * ldc + c_off + n] = hi;
            Xh[(size_t)r0 * xld + x_off + n]       = __float2half_rn(lo);
            Xh[(size_t)(r0 + 1) * xld + x_off + n] = __float2half_rn(hi);
        }
    }
}

// ======================= weight prep (all 3 layers, fp16 hi/lo) ============
__global__ void prep_w3(
    const float* __restrict__ W0, const float* __restrict__ b0,
    const float* __restrict__ W1, const float* __restrict__ b1,
    const float* __restrict__ W2, const float* __restrict__ b2,
    __half* __restrict__ Wh, __half* __restrict__ Wl,
    float* __restrict__ biasL)
{
    const int layer = blockIdx.y;
    const float* W = (layer == 0) ? W0 : (layer == 1) ? W1 : W2;
    const float* b = (layer == 0) ? b0 : (layer == 1) ? b1 : b2;
    const int Kin  = (layer == 0) ? INDIM : LDIM;

    __half* wh = Wh + (size_t)layer * WSTRIDE;
    __half* wl = Wl + (size_t)layer * WSTRIDE;

    int idx = blockIdx.x * blockDim.x + threadIdx.x;
    if (idx < 512 * Kin) {
        int r = idx / Kin, c = idx % Kin;
        float vl = W[(size_t)r * 2 * Kin + c];
        float vr = W[(size_t)r * 2 * Kin + Kin + c];
        float d  = vr - vl;

        __half h = __float2half_rn(vl);
        wh[(size_t)r * Kin + c] = h;
        wl[(size_t)r * Kin + c] = __float2half_rn(vl - __half2float(h));
        h = __float2half_rn(d);
        wh[(size_t)(512 + r) * Kin + c] = h;
        wl[(size_t)(512 + r) * Kin + c] = __float2half_rn(d - __half2float(h));
    }
    if (idx < 512) {
        biasL[layer * 1024 + idx]       = 0.0f;
        biasL[layer * 1024 + 512 + idx] = b[idx];
    }
}

// ------- pooled prologue: out[:,0:256] = pooled; X0h[:,0:256] = fp16 ------
__global__ void pool_pre(const float* __restrict__ pooled,
                         float* __restrict__ out,
                         __half* __restrict__ X0h)
{
    int idx = blockIdx.x * blockDim.x + threadIdx.x;
    if (idx >= NNODES * CPOOL) return;
    int n = idx >> 8;           // / 256
    int c = idx & 255;
    float v = pooled[idx];
    out[(size_t)n * OUTLD + c] = v;
    X0h[(size_t)n * INDIM + c] = __float2half_rn(v);
}

// ---------------- aggregation (fp16 D) + fp16 convert of new features -----
__global__ __launch_bounds__(128) void aggregate(
    const __half* __restrict__ D,
    const int*   __restrict__ src,
    __half* __restrict__ Xh,         // 4096 x 512
    float* __restrict__ out,         // 4096 x 1920
    int out_off)
{
    const int n  = blockIdx.x;
    const int f4 = threadIdx.x;   // 0..127, covers 4 halves (8B) each

    uint2 cw = *(const uint2*)(D + (size_t)n * 1024 + 512 + f4 * 4);
    float2 c01 = __half22float2(*(__half2*)&cw.x);
    float2 c23 = __half22float2(*(__half2*)&cw.y);
    float4 m = make_float4(0.f, 0.f, 0.f, 0.f);

    #pragma unroll
    for (int k = 0; k < KNBR; k++) {
        int j = src[n * KNBR + k];
        uint2 aw = *(const uint2*)(D + (size_t)j * 1024 + f4 * 4);
        float2 a01 = __half22float2(*(__half2*)&aw.x);
        float2 a23 = __half22float2(*(__half2*)&aw.y);
        m.x = fmaxf(m.x, a01.x + c01.x);
        m.y = fmaxf(m.y, a01.y + c01.y);
        m.z = fmaxf(m.z, a23.x + c23.x);
        m.w = fmaxf(m.w, a23.y + c23.y);
    }
    *reinterpret_cast<float4*>(out + (size_t)n * OUTLD + out_off + f4 * 4) = m;

    __half2 h01 = __floats2half2_rn(m.x, m.y);
    __half2 h23 = __floats2half2_rn(m.z, m.w);
    *reinterpret_cast<__half2*>(Xh + (size_t)n * LDIM + f4 * 4)     = h01;
    *reinterpret_cast<__half2*>(Xh + (size_t)n * LDIM + f4 * 4 + 2) = h23;
}

// ---------------------------------------------------------------------------
extern "C" void kernel_launch(void* const* d_in, const int* in_sizes, int n_in,
                              void* d_out, int out_size)
{
    const float* rois   = (const float*)d_in[0];
    const float* pooled = (const float*)d_in[1];
    const int*   edge   = (const int*)  d_in[2];   // (2, 65536): row 0 = src
    const float* gW1    = (const float*)d_in[3];
    const float* gb1    = (const float*)d_in[4];
    const float* gW2    = (const float*)d_in[5];
    const float* gb2    = (const float*)d_in[6];
    const float* fcW[3] = {(const float*)d_in[7], (const float*)d_in[9],  (const float*)d_in[11]};
    const float* fcb[3] = {(const float*)d_in[8], (const float*)d_in[10], (const float*)d_in[12]};
    float* out = (float*)d_out;

    const int* src = edge;

    float *H, *biasL;
    __half *D, *X0h, *Xh, *Wh, *Wl;
    cudaGetSymbolAddress((void**)&H,     g_H);
    cudaGetSymbolAddress((void**)&D,     g_D);
    cudaGetSymbolAddress((void**)&biasL, g_biasL);
    cudaGetSymbolAddress((void**)&X0h,   g_X0h);
    cudaGetSymbolAddress((void**)&Xh,    g_Xh);
    cudaGetSymbolAddress((void**)&Wh,    g_Wh);
    cudaGetSymbolAddress((void**)&Wl,    g_Wl);

    cudaFuncSetAttribute(gemm_mma, cudaFuncAttributeMaxDynamicSharedMemorySize, GEMM_SMEM);

    // 1) pooled prologue (independent of everything)
    pool_pre<<<(NNODES * CPOOL + 255) / 256, 256>>>(pooled, out, X0h);

    // 2) all weight prep (independent of activations)
    prep_w3<<<dim3(1024, 3), 256>>>(
        fcW[0], fcb[0], fcW[1], fcb[1], fcW[2], fcb[2], Wh, Wl, biasL);

    // 3) geo MLP layer 1: H = relu(rois @ gW1.T + gb1)
    sgemm_tn<<<dim3(GDIM / TN, NNODES / TM), dim3(16, 16)>>>(
        rois, 7, gW1, 7, gb1, H, GDIM, 0, NNODES, GDIM, 7, 1);

    // 4) geo MLP layer 2: out[:,256:384] = relu(...); X0h[:,256:384] = fp16
    sgemm_f2<<<dim3(GDIM / BN, NNODES / BM), 256>>>(
        H, GDIM, gW2, GDIM, gb2, out, OUTLD, CPOOL, X0h, INDIM, CPOOL, GDIM);

    // 5) three EdgeConv layers
    const int Kin[3]    = {INDIM, LDIM, LDIM};
    const int outOff[3] = {384, 384 + 512, 384 + 1024};

    for (int l = 0; l < 3; l++) {
        const __half* Ain = (l == 0) ? X0h : Xh;
        gemm_mma<<<dim3(1024 / 128, NNODES / 128), 256, GEMM_SMEM>>>(
            Ain, Wh + (size_t)l * WSTRIDE, Wl + (size_t)l * WSTRIDE,
            biasL + l * 1024, D, Kin[l]);

        aggregate<<<NNODES, 128>>>(D, src, Xh, out, outOff[l]);
    }
}

// round 12
// speedup vs baseline: 1.7041x; 1.0142x over previous
#include <cuda_runtime.h>
#include <cuda_bf16.h>
#include <cuda_fp16.h>
#include <cstdint>

// Problem constants
#define NNODES 4096       // B*N = 8*512
#define KNBR   16
#define CPOOL  256
#define GDIM   128
#define INDIM  384        // CPOOL + GDIM
#define LDIM   512
#define OUTLD  1920       // 384 + 3*512
#define WSTRIDE (1024 * 512)

// ---------------- device scratch (no allocations allowed) ----------------
__device__ float g_biasL[3 * 1024];
__device__ __align__(16) __half g_D  [NNODES * 1024];
__device__ __align__(16) __half g_X0h[NNODES * INDIM];
__device__ __align__(16) __half g_Xh [NNODES * LDIM];
__device__ __align__(16) __half g_Wh [3 * WSTRIDE];
__device__ __align__(16) __half g_Wl [3 * WSTRIDE];

// ======================= helpers =======================
__device__ __forceinline__ uint32_t smem_u32(const void* p) {
    uint32_t a;
    asm("{ .reg .u64 t; cvta.to.shared.u64 t, %1; cvt.u32.u64 %0, t; }"
        : "=r"(a) : "l"(p));
    return a;
}
__device__ __forceinline__ uint32_t sw64(uint32_t o) {   // SW64 swizzle for 64B rows
    return o ^ ((o >> 3) & 0x30);
}
__device__ __forceinline__ void cp16(uint32_t dst, const void* src) {
    asm volatile("cp.async.cg.shared.global [%0], [%1], 16;" :: "r"(dst), "l"(src));
}
#define CP_COMMIT() asm volatile("cp.async.commit_group;" ::: "memory")
#define CP_WAIT(n)  asm volatile("cp.async.wait_group %0;" :: "n"(n) : "memory")

#define LDSM4(r, a) \
    asm volatile("ldmatrix.sync.aligned.m8n8.x4.shared.b16 {%0,%1,%2,%3}, [%4];" \
        : "=r"((r)[0]), "=r"((r)[1]), "=r"((r)[2]), "=r"((r)[3]) : "r"(a))

#define MMAF16(d, a, b0, b1) \
    asm volatile("mma.sync.aligned.m16n8k16.row.col.f32.f16.f16.f32 " \
        "{%0,%1,%2,%3}, {%4,%5,%6,%7}, {%8,%9}, {%0,%1,%2,%3};" \
        : "+f"((d)[0]), "+f"((d)[1]), "+f"((d)[2]), "+f"((d)[3]) \
        : "r"((a)[0]), "r"((a)[1]), "r"((a)[2]), "r"((a)[3]), "r"(b0), "r"(b1))

// ======================= mma.sync GEMM (fp16, 2-pass) ======================
// D(4096 x 1024, fp16) = X(4096 x Kin) @ W(1024 x Kin)^T + bias
// A = activations rounded to fp16; W split into fp16 hi + lo (exact).
// D = A*Wh + A*Wl, fp32 accumulation, fp16 store.
// CTA tile 128x128, BK=32, 8 warps (warp tile 32x64), cp.async double buffer.
#define ARR_BYTES (128 * 64)                // 8192
#define STG_BYTES (3 * ARR_BYTES)           // 24576
#define GEMM_SMEM (2 * STG_BYTES)           // 49152

__global__ __launch_bounds__(256) void gemm_mma(
    const __half* __restrict__ A,
    const __half* __restrict__ Bh, const __half* __restrict__ Bl,
    const float* __restrict__ bias,
    __half* __restrict__ C,     // ldc = 1024, fp16
    int Kin)
{
    extern __shared__ char smem[];
    const uint32_t sb  = smem_u32(smem);
    const int tid  = threadIdx.x;
    const int lane = tid & 31;
    const int wid  = tid >> 5;
    const int bm   = blockIdx.y * 128;
    const int bn   = blockIdx.x * 128;
    const int m0   = (wid & 3) * 32;     // warp m-offset in tile
    const int n0   = (wid >> 2) * 64;    // warp n-offset in tile

    // cp.async chunk mapping: 512 chunks of 16B per array, 2 per thread
    const int r0c = tid >> 2;            // rows 0..63
    const int s0c = tid & 3;             // seg 0..3
    const int r1c = (tid + 256) >> 2;    // rows 64..127

    const __half* gsrc[3] = { A, Bh, Bl };
    const int grow0[3] = { bm, bn, bn };

    uint32_t soff0[3], soff1[3];
    #pragma unroll
    for (int a = 0; a < 3; a++) {
        soff0[a] = a * ARR_BYTES + sw64((uint32_t)(r0c * 64 + s0c * 16));
        soff1[a] = a * ARR_BYTES + sw64((uint32_t)(r1c * 64 + s0c * 16));
    }

    const int nk = Kin / 32;

    // ---- issue stage 0 ----
    {
        const uint32_t bufb = sb;
        #pragma unroll
        for (int a = 0; a < 3; a++) {
            cp16(bufb + soff0[a], gsrc[a] + (size_t)(grow0[a] + r0c) * Kin + s0c * 8);
            cp16(bufb + soff1[a], gsrc[a] + (size_t)(grow0[a] + r1c) * Kin + s0c * 8);
        }
        CP_COMMIT();
    }

    float acc[2][8][4];
    #pragma unroll
    for (int i = 0; i < 2; i++)
        #pragma unroll
        for (int j = 0; j < 8; j++)
            #pragma unroll
            for (int q = 0; q < 4; q++)
                acc[i][j][q] = 0.0f;

    // ldmatrix per-lane address components
    const int a_row = lane & 15;
    const int a_kh  = (lane >> 4) & 1;
    const int b_row = ((lane >> 4) << 3) + (lane & 7);
    const int b_kh  = (lane >> 3) & 1;

    for (int s = 0; s < nk; s++) {
        const uint32_t bufb = sb + (uint32_t)(s & 1) * STG_BYTES;

        if (s + 1 < nk) {
            const uint32_t nb = sb + (uint32_t)((s + 1) & 1) * STG_BYTES;
            const int kb = (s + 1) * 32;
            #pragma unroll
            for (int a = 0; a < 3; a++) {
                cp16(nb + soff0[a], gsrc[a] + (size_t)(grow0[a] + r0c) * Kin + kb + s0c * 8);
                cp16(nb + soff1[a], gsrc[a] + (size_t)(grow0[a] + r1c) * Kin + kb + s0c * 8);
            }
            CP_COMMIT();
            CP_WAIT(1);
        } else {
            CP_WAIT(0);
        }
        __syncthreads();

        #pragma unroll
        for (int kk = 0; kk < 2; kk++) {
            uint32_t fa[2][4];
            #pragma unroll
            for (int mt = 0; mt < 2; mt++) {
                const uint32_t off =
                    sw64((uint32_t)((m0 + mt * 16 + a_row) * 64 + kk * 32 + a_kh * 16));
                LDSM4(fa[mt], bufb + 0 * ARR_BYTES + off);
            }
            uint32_t fbh[4][4], fbl[4][4];
            #pragma unroll
            for (int nt = 0; nt < 4; nt++) {
                const uint32_t off =
                    sw64((uint32_t)((n0 + nt * 16 + b_row) * 64 + kk * 32 + b_kh * 16));
                LDSM4(fbh[nt], bufb + 1 * ARR_BYTES + off);
                LDSM4(fbl[nt], bufb + 2 * ARR_BYTES + off);
            }
            #pragma unroll
            for (int mt = 0; mt < 2; mt++) {
                #pragma unroll
                for (int ni = 0; ni < 8; ni++) {
                    const uint32_t bh0 = fbh[ni >> 1][(ni & 1) * 2];
                    const uint32_t bh1 = fbh[ni >> 1][(ni & 1) * 2 + 1];
                    const uint32_t bl0 = fbl[ni >> 1][(ni & 1) * 2];
                    const uint32_t bl1 = fbl[ni >> 1][(ni & 1) * 2 + 1];
                    MMAF16(acc[mt][ni], fa[mt], bh0, bh1);
                    MMAF16(acc[mt][ni], fa[mt], bl0, bl1);
                }
            }
        }
        __syncthreads();
    }

    // ---- epilogue: write D (fp16) with bias ----
    #pragma unroll
    for (int mt = 0; mt < 2; mt++) {
        const int r = bm + m0 + mt * 16 + (lane >> 2);
        #pragma unroll
        for (int ni = 0; ni < 8; ni++) {
            const int col = bn + n0 + ni * 8 + (lane & 3) * 2;
            const float b0 = bias[col], b1 = bias[col + 1];
            __half2 v0 = __floats2half2_rn(acc[mt][ni][0] + b0, acc[mt][ni][1] + b1);
            __half2 v1 = __floats2half2_rn(acc[mt][ni][2] + b0, acc[mt][ni][3] + b1);
            *(__half2*)(C + (size_t)r * 1024 + col)       = v0;
            *(__half2*)(C + (size_t)(r + 8) * 1024 + col) = v1;
        }
    }
}

// ======================= fused geo prologue =======================
// One kernel replaces sgemm_tn + sgemm_f2 + pool_pre.
// 256 blocks x 128 threads; each block handles 16 nodes:
//   layer1: h = relu(W1 @ roi + b1)            (smem)
//   layer2: g = relu(W2 @ h + b2)              (W2 transposed in smem,
//                                               register-blocked over 16 nodes)
//   writes: out[:,256:384] fp32 + X0h[:,256:384] fp16
//           out[:,0:256]   = pooled, X0h[:,0:256] = fp16(pooled)
#define GEO_NODES 16
// smem floats: W2T 128*129 | W1 896 | b1 128 | b2 128 | roi 16*8 | h 16*132
#define GEO_W2T   0
#define GEO_W1    (128 * 129)
#define GEO_B1    (GEO_W1 + 896)
#define GEO_B2    (GEO_B1 + 128)
#define GEO_ROI   (GEO_B2 + 128)
#define GEO_H     (GEO_ROI + 128)
#define GEO_SMEMF (GEO_H + GEO_NODES * 132)
#define GEO_SMEM  (GEO_SMEMF * 4)

__global__ __launch_bounds__(128) void geo_pre(
    const float* __restrict__ rois,
    const float* __restrict__ pooled,
    const float* __restrict__ gW1, const float* __restrict__ gb1,
    const float* __restrict__ gW2, const float* __restrict__ gb2,
    float* __restrict__ out,
    __half* __restrict__ X0h)
{
    extern __shared__ float s[];
    const int tid = threadIdx.x;
    const int n0  = blockIdx.x * GEO_NODES;

    // W2 transposed into smem (pad 129 -> conflict-free write & read)
    for (int i = tid; i < 128 * 128; i += 128) {
        int r = i >> 7, c = i & 127;
        s[GEO_W2T + c * 129 + r] = gW2[i];
    }
    for (int i = tid; i < 896; i += 128) s[GEO_W1 + i] = gW1[i];
    s[GEO_B1 + tid] = gb1[tid];
    s[GEO_B2 + tid] = gb2[tid];
    if (tid < GEO_NODES * 7) {
        int node = tid / 7, j = tid - node * 7;
        s[GEO_ROI + node * 8 + j] = rois[(size_t)(n0 + node) * 7 + j];
    }
    __syncthreads();

    // layer 1: h_s[node][tid] = relu(W1[tid,:] . roi[node] + b1[tid])
    #pragma unroll
    for (int node = 0; node < GEO_NODES; node++) {
        float a = s[GEO_B1 + tid];
        #pragma unroll
        for (int j = 0; j < 7; j++)
            a = fmaf(s[GEO_W1 + tid * 7 + j], s[GEO_ROI + node * 8 + j], a);
        s[GEO_H + node * 132 + tid] = fmaxf(a, 0.0f);
    }
    __syncthreads();

    // layer 2: register-blocked, W2T value reused across 16 nodes
    float acc[GEO_NODES];
    #pragma unroll
    for (int node = 0; node < GEO_NODES; node++) acc[node] = s[GEO_B2 + tid];

    #pragma unroll 8
    for (int j = 0; j < 128; j += 4) {
        const float w0 = s[GEO_W2T + (j + 0) * 129 + tid];
        const float w1 = s[GEO_W2T + (j + 1) * 129 + tid];
        const float w2 = s[GEO_W2T + (j + 2) * 129 + tid];
        const float w3 = s[GEO_W2T + (j + 3) * 129 + tid];
        #pragma unroll
        for (int node = 0; node < GEO_NODES; node++) {
            float4 h = *(const float4*)&s[GEO_H + node * 132 + j];
            float a = acc[node];
            a = fmaf(w0, h.x, a);
            a = fmaf(w1, h.y, a);
            a = fmaf(w2, h.z, a);
            a = fmaf(w3, h.w, a);
            acc[node] = a;
        }
    }

    // epilogue: g + pooled copy, coalesced per node
    #pragma unroll
    for (int node = 0; node < GEO_NODES; node++) {
        const int n = n0 + node;
        const float g = fmaxf(acc[node], 0.0f);
        out[(size_t)n * OUTLD + CPOOL + tid] = g;
        X0h[(size_t)n * INDIM + CPOOL + tid] = __float2half_rn(g);

        const float v0 = pooled[(size_t)n * CPOOL + tid];
        const float v1 = pooled[(size_t)n * CPOOL + tid + 128];
        out[(size_t)n * OUTLD + tid]       = v0;
        out[(size_t)n * OUTLD + tid + 128] = v1;
        X0h[(size_t)n * INDIM + tid]       = __float2half_rn(v0);
        X0h[(size_t)n * INDIM + tid + 128] = __float2half_rn(v1);
    }
}

// ======================= weight prep (all 3 layers, fp16 hi/lo) ============
__global__ void prep_w3(
    const float* __restrict__ W0, const float* __restrict__ b0,
    const float* __restrict__ W1, const float* __restrict__ b1,
    const float* __restrict__ W2, const float* __restrict__ b2,
    __half* __restrict__ Wh, __half* __restrict__ Wl,
    float* __restrict__ biasL)
{
    const int layer = blockIdx.y;
    const float* W = (layer == 0) ? W0 : (layer == 1) ? W1 : W2;
    const float* b = (layer == 0) ? b0 : (layer == 1) ? b1 : b2;
    const int Kin  = (layer == 0) ? INDIM : LDIM;

    __half* wh = Wh + (size_t)layer * WSTRIDE;
    __half* wl = Wl + (size_t)layer * WSTRIDE;

    int idx = blockIdx.x * blockDim.x + threadIdx.x;
    if (idx < 512 * Kin) {
        int r = idx / Kin, c = idx % Kin;
        float vl = W[(size_t)r * 2 * Kin + c];
        float vr = W[(size_t)r * 2 * Kin + Kin + c];
        float d  = vr - vl;

        __half h = __float2half_rn(vl);
        wh[(size_t)r * Kin + c] = h;
        wl[(size_t)r * Kin + c] = __float2half_rn(vl - __half2float(h));
        h = __float2half_rn(d);
        wh[(size_t)(512 + r) * Kin + c] = h;
        wl[(size_t)(512 + r) * Kin + c] = __float2half_rn(d - __half2float(h));
    }
    if (idx < 512) {
        biasL[layer * 1024 + idx]       = 0.0f;
        biasL[layer * 1024 + 512 + idx] = b[idx];
    }
}

// ---------------- aggregation (fp16 D) + fp16 convert of new features -----
__global__ __launch_bounds__(128) void aggregate(
    const __half* __restrict__ D,
    const int*   __restrict__ src,
    __half* __restrict__ Xh,         // 4096 x 512
    float* __restrict__ out,         // 4096 x 1920
    int out_off)
{
    const int n  = blockIdx.x;
    const int f4 = threadIdx.x;   // 0..127, covers 4 halves (8B) each

    uint2 cw = *(const uint2*)(D + (size_t)n * 1024 + 512 + f4 * 4);
    float2 c01 = __half22float2(*(__half2*)&cw.x);
    float2 c23 = __half22float2(*(__half2*)&cw.y);
    float4 m = make_float4(0.f, 0.f, 0.f, 0.f);

    #pragma unroll
    for (int k = 0; k < KNBR; k++) {
        int j = src[n * KNBR + k];
        uint2 aw = *(const uint2*)(D + (size_t)j * 1024 + f4 * 4);
        float2 a01 = __half22float2(*(__half2*)&aw.x);
        float2 a23 = __half22float2(*(__half2*)&aw.y);
        m.x = fmaxf(m.x, a01.x + c01.x);
        m.y = fmaxf(m.y, a01.y + c01.y);
        m.z = fmaxf(m.z, a23.x + c23.x);
        m.w = fmaxf(m.w, a23.y + c23.y);
    }
    *reinterpret_cast<float4*>(out + (size_t)n * OUTLD + out_off + f4 * 4) = m;

    __half2 h01 = __floats2half2_rn(m.x, m.y);
    __half2 h23 = __floats2half2_rn(m.z, m.w);
    *reinterpret_cast<__half2*>(Xh + (size_t)n * LDIM + f4 * 4)     = h01;
    *reinterpret_cast<__half2*>(Xh + (size_t)n * LDIM + f4 * 4 + 2) = h23;
}

// ---------------------------------------------------------------------------
extern "C" void kernel_launch(void* const* d_in, const int* in_sizes, int n_in,
                              void* d_out, int out_size)
{
    const float* rois   = (const float*)d_in[0];
    const float* pooled = (const float*)d_in[1];
    const int*   edge   = (const int*)  d_in[2];   // (2, 65536): row 0 = src
    const float* gW1    = (const float*)d_in[3];
    const float* gb1    = (const float*)d_in[4];
    const float* gW2    = (const float*)d_in[5];
    const float* gb2    = (const float*)d_in[6];
    const float* fcW[3] = {(const float*)d_in[7], (const float*)d_in[9],  (const float*)d_in[11]};
    const float* fcb[3] = {(const float*)d_in[8], (const float*)d_in[10], (const float*)d_in[12]};
    float* out = (float*)d_out;

    const int* src = edge;

    float *biasL;
    __half *D, *X0h, *Xh, *Wh, *Wl;
    cudaGetSymbolAddress((void**)&D,     g_D);
    cudaGetSymbolAddress((void**)&biasL, g_biasL);
    cudaGetSymbolAddress((void**)&X0h,   g_X0h);
    cudaGetSymbolAddress((void**)&Xh,    g_Xh);
    cudaGetSymbolAddress((void**)&Wh,    g_Wh);
    cudaGetSymbolAddress((void**)&Wl,    g_Wl);

    cudaFuncSetAttribute(gemm_mma, cudaFuncAttributeMaxDynamicSharedMemorySize, GEMM_SMEM);
    cudaFuncSetAttribute(geo_pre,  cudaFuncAttributeMaxDynamicSharedMemorySize, GEO_SMEM);

    // 1) fused geo prologue (replaces sgemm_tn + sgemm_f2 + pool_pre)
    geo_pre<<<NNODES / GEO_NODES, 128, GEO_SMEM>>>(
        rois, pooled, gW1, gb1, gW2, gb2, out, X0h);

    // 2) all weight prep (independent of activations)
    prep_w3<<<dim3(1024, 3), 256>>>(
        fcW[0], fcb[0], fcW[1], fcb[1], fcW[2], fcb[2], Wh, Wl, biasL);

    // 3) three EdgeConv layers
    const int Kin[3]    = {INDIM, LDIM, LDIM};
    const int outOff[3] = {384, 384 + 512, 384 + 1024};

    for (int l = 0; l < 3; l++) {
        const __half* Ain = (l == 0) ? X0h : Xh;
        gemm_mma<<<dim3(1024 / 128, NNODES / 128), 256, GEMM_SMEM>>>(
            Ain, Wh + (size_t)l * WSTRIDE, Wl + (size_t)l * WSTRIDE,
            biasL + l * 1024, D, Kin[l]);

        aggregate<<<NNODES, 128>>>(D, src, Xh, out, outOff[l]);
    }
}

// round 13
// speedup vs baseline: 1.7324x; 1.0166x over previous
#include <cuda_runtime.h>
#include <cuda_bf16.h>
#include <cuda_fp16.h>
#include <cstdint>

// Problem constants
#define NNODES 4096       // B*N = 8*512
#define KNBR   16
#define CPOOL  256
#define GDIM   128
#define INDIM  384        // CPOOL + GDIM
#define LDIM   512
#define OUTLD  1920       // 384 + 3*512
#define WSTRIDE (1024 * 512)

// ---------------- device scratch (no allocations allowed) ----------------
__device__ float g_biasL[3 * 1024];
__device__ __align__(16) __half g_D  [NNODES * 1024];
__device__ __align__(16) __half g_X0h[NNODES * INDIM];
__device__ __align__(16) __half g_Xh [NNODES * LDIM];
__device__ __align__(16) __half g_Wh [3 * WSTRIDE];
__device__ __align__(16) __half g_Wl [3 * WSTRIDE];

// ======================= helpers =======================
__device__ __forceinline__ uint32_t smem_u32(const void* p) {
    uint32_t a;
    asm("{ .reg .u64 t; cvta.to.shared.u64 t, %1; cvt.u32.u64 %0, t; }"
        : "=r"(a) : "l"(p));
    return a;
}
__device__ __forceinline__ uint32_t sw64(uint32_t o) {   // SW64 swizzle for 64B rows
    return o ^ ((o >> 3) & 0x30);
}
__device__ __forceinline__ void cp16(uint32_t dst, const void* src) {
    asm volatile("cp.async.cg.shared.global [%0], [%1], 16;" :: "r"(dst), "l"(src));
}
#define CP_COMMIT() asm volatile("cp.async.commit_group;" ::: "memory")
#define CP_WAIT(n)  asm volatile("cp.async.wait_group %0;" :: "n"(n) : "memory")

#define LDSM4(r, a) \
    asm volatile("ldmatrix.sync.aligned.m8n8.x4.shared.b16 {%0,%1,%2,%3}, [%4];" \
        : "=r"((r)[0]), "=r"((r)[1]), "=r"((r)[2]), "=r"((r)[3]) : "r"(a))

#define MMAF16(d, a, b0, b1) \
    asm volatile("mma.sync.aligned.m16n8k16.row.col.f32.f16.f16.f32 " \
        "{%0,%1,%2,%3}, {%4,%5,%6,%7}, {%8,%9}, {%0,%1,%2,%3};" \
        : "+f"((d)[0]), "+f"((d)[1]), "+f"((d)[2]), "+f"((d)[3]) \
        : "r"((a)[0]), "r"((a)[1]), "r"((a)[2]), "r"((a)[3]), "r"(b0), "r"(b1))

// ======================= mma.sync GEMM (fp16, 2-pass) ======================
// D(4096 x 1024, fp16) = X(4096 x Kin) @ W(1024 x Kin)^T + bias
// A = activations rounded to fp16; W split into fp16 hi + lo (exact).
// D = A*Wh + A*Wl, fp32 accumulation, fp16 store.
// CTA tile 128x128, BK=32, 8 warps (warp tile 32x64), cp.async double buffer.
#define ARR_BYTES (128 * 64)                // 8192
#define STG_BYTES (3 * ARR_BYTES)           // 24576
#define GEMM_SMEM (2 * STG_BYTES)           // 49152

__global__ __launch_bounds__(256) void gemm_mma(
    const __half* __restrict__ A,
    const __half* __restrict__ Bh, const __half* __restrict__ Bl,
    const float* __restrict__ bias,
    __half* __restrict__ C,     // ldc = 1024, fp16
    int Kin)
{
    extern __shared__ char smem[];
    const uint32_t sb  = smem_u32(smem);
    const int tid  = threadIdx.x;
    const int lane = tid & 31;
    const int wid  = tid >> 5;
    const int bm   = blockIdx.y * 128;
    const int bn   = blockIdx.x * 128;
    const int m0   = (wid & 3) * 32;     // warp m-offset in tile
    const int n0   = (wid >> 2) * 64;    // warp n-offset in tile

    // cp.async chunk mapping: 512 chunks of 16B per array, 2 per thread
    const int r0c = tid >> 2;            // rows 0..63
    const int s0c = tid & 3;             // seg 0..3
    const int r1c = (tid + 256) >> 2;    // rows 64..127

    const __half* gsrc[3] = { A, Bh, Bl };
    const int grow0[3] = { bm, bn, bn };

    uint32_t soff0[3], soff1[3];
    #pragma unroll
    for (int a = 0; a < 3; a++) {
        soff0[a] = a * ARR_BYTES + sw64((uint32_t)(r0c * 64 + s0c * 16));
        soff1[a] = a * ARR_BYTES + sw64((uint32_t)(r1c * 64 + s0c * 16));
    }

    const int nk = Kin / 32;

    // ---- issue stage 0 ----
    {
        const uint32_t bufb = sb;
        #pragma unroll
        for (int a = 0; a < 3; a++) {
            cp16(bufb + soff0[a], gsrc[a] + (size_t)(grow0[a] + r0c) * Kin + s0c * 8);
            cp16(bufb + soff1[a], gsrc[a] + (size_t)(grow0[a] + r1c) * Kin + s0c * 8);
        }
        CP_COMMIT();
    }

    float acc[2][8][4];
    #pragma unroll
    for (int i = 0; i < 2; i++)
        #pragma unroll
        for (int j = 0; j < 8; j++)
            #pragma unroll
            for (int q = 0; q < 4; q++)
                acc[i][j][q] = 0.0f;

    // ldmatrix per-lane address components
    const int a_row = lane & 15;
    const int a_kh  = (lane >> 4) & 1;
    const int b_row = ((lane >> 4) << 3) + (lane & 7);
    const int b_kh  = (lane >> 3) & 1;

    for (int s = 0; s < nk; s++) {
        const uint32_t bufb = sb + (uint32_t)(s & 1) * STG_BYTES;

        if (s + 1 < nk) {
            const uint32_t nb = sb + (uint32_t)((s + 1) & 1) * STG_BYTES;
            const int kb = (s + 1) * 32;
            #pragma unroll
            for (int a = 0; a < 3; a++) {
                cp16(nb + soff0[a], gsrc[a] + (size_t)(grow0[a] + r0c) * Kin + kb + s0c * 8);
                cp16(nb + soff1[a], gsrc[a] + (size_t)(grow0[a] + r1c) * Kin + kb + s0c * 8);
            }
            CP_COMMIT();
            CP_WAIT(1);
        } else {
            CP_WAIT(0);
        }
        __syncthreads();

        #pragma unroll
        for (int kk = 0; kk < 2; kk++) {
            uint32_t fa[2][4];
            #pragma unroll
            for (int mt = 0; mt < 2; mt++) {
                const uint32_t off =
                    sw64((uint32_t)((m0 + mt * 16 + a_row) * 64 + kk * 32 + a_kh * 16));
                LDSM4(fa[mt], bufb + 0 * ARR_BYTES + off);
            }
            uint32_t fbh[4][4], fbl[4][4];
            #pragma unroll
            for (int nt = 0; nt < 4; nt++) {
                const uint32_t off =
                    sw64((uint32_t)((n0 + nt * 16 + b_row) * 64 + kk * 32 + b_kh * 16));
                LDSM4(fbh[nt], bufb + 1 * ARR_BYTES + off);
                LDSM4(fbl[nt], bufb + 2 * ARR_BYTES + off);
            }
            #pragma unroll
            for (int mt = 0; mt < 2; mt++) {
                #pragma unroll
                for (int ni = 0; ni < 8; ni++) {
                    const uint32_t bh0 = fbh[ni >> 1][(ni & 1) * 2];
                    const uint32_t bh1 = fbh[ni >> 1][(ni & 1) * 2 + 1];
                    const uint32_t bl0 = fbl[ni >> 1][(ni & 1) * 2];
                    const uint32_t bl1 = fbl[ni >> 1][(ni & 1) * 2 + 1];
                    MMAF16(acc[mt][ni], fa[mt], bh0, bh1);
                    MMAF16(acc[mt][ni], fa[mt], bl0, bl1);
                }
            }
        }
        __syncthreads();
    }

    // ---- epilogue: write D (fp16) with bias ----
    #pragma unroll
    for (int mt = 0; mt < 2; mt++) {
        const int r = bm + m0 + mt * 16 + (lane >> 2);
        #pragma unroll
        for (int ni = 0; ni < 8; ni++) {
            const int col = bn + n0 + ni * 8 + (lane & 3) * 2;
            const float b0 = bias[col], b1 = bias[col + 1];
            __half2 v0 = __floats2half2_rn(acc[mt][ni][0] + b0, acc[mt][ni][1] + b1);
            __half2 v1 = __floats2half2_rn(acc[mt][ni][2] + b0, acc[mt][ni][3] + b1);
            *(__half2*)(C + (size_t)r * 1024 + col)       = v0;
            *(__half2*)(C + (size_t)(r + 8) * 1024 + col) = v1;
        }
    }
}

// ======================= fused geo prologue =======================
#define GEO_NODES 16
#define GEO_W2T   0
#define GEO_W1    (128 * 129)
#define GEO_B1    (GEO_W1 + 896)
#define GEO_B2    (GEO_B1 + 128)
#define GEO_ROI   (GEO_B2 + 128)
#define GEO_H     (GEO_ROI + 128)
#define GEO_SMEMF (GEO_H + GEO_NODES * 132)
#define GEO_SMEM  (GEO_SMEMF * 4)

__global__ __launch_bounds__(128) void geo_pre(
    const float* __restrict__ rois,
    const float* __restrict__ pooled,
    const float* __restrict__ gW1, const float* __restrict__ gb1,
    const float* __restrict__ gW2, const float* __restrict__ gb2,
    float* __restrict__ out,
    __half* __restrict__ X0h)
{
    extern __shared__ float s[];
    const int tid = threadIdx.x;
    const int n0  = blockIdx.x * GEO_NODES;

    for (int i = tid; i < 128 * 128; i += 128) {
        int r = i >> 7, c = i & 127;
        s[GEO_W2T + c * 129 + r] = gW2[i];
    }
    for (int i = tid; i < 896; i += 128) s[GEO_W1 + i] = gW1[i];
    s[GEO_B1 + tid] = gb1[tid];
    s[GEO_B2 + tid] = gb2[tid];
    if (tid < GEO_NODES * 7) {
        int node = tid / 7, j = tid - node * 7;
        s[GEO_ROI + node * 8 + j] = rois[(size_t)(n0 + node) * 7 + j];
    }
    __syncthreads();

    #pragma unroll
    for (int node = 0; node < GEO_NODES; node++) {
        float a = s[GEO_B1 + tid];
        #pragma unroll
        for (int j = 0; j < 7; j++)
            a = fmaf(s[GEO_W1 + tid * 7 + j], s[GEO_ROI + node * 8 + j], a);
        s[GEO_H + node * 132 + tid] = fmaxf(a, 0.0f);
    }
    __syncthreads();

    float acc[GEO_NODES];
    #pragma unroll
    for (int node = 0; node < GEO_NODES; node++) acc[node] = s[GEO_B2 + tid];

    #pragma unroll 8
    for (int j = 0; j < 128; j += 4) {
        const float w0 = s[GEO_W2T + (j + 0) * 129 + tid];
        const float w1 = s[GEO_W2T + (j + 1) * 129 + tid];
        const float w2 = s[GEO_W2T + (j + 2) * 129 + tid];
        const float w3 = s[GEO_W2T + (j + 3) * 129 + tid];
        #pragma unroll
        for (int node = 0; node < GEO_NODES; node++) {
            float4 h = *(const float4*)&s[GEO_H + node * 132 + j];
            float a = acc[node];
            a = fmaf(w0, h.x, a);
            a = fmaf(w1, h.y, a);
            a = fmaf(w2, h.z, a);
            a = fmaf(w3, h.w, a);
            acc[node] = a;
        }
    }

    #pragma unroll
    for (int node = 0; node < GEO_NODES; node++) {
        const int n = n0 + node;
        const float g = fmaxf(acc[node], 0.0f);
        out[(size_t)n * OUTLD + CPOOL + tid] = g;
        X0h[(size_t)n * INDIM + CPOOL + tid] = __float2half_rn(g);

        const float v0 = pooled[(size_t)n * CPOOL + tid];
        const float v1 = pooled[(size_t)n * CPOOL + tid + 128];
        out[(size_t)n * OUTLD + tid]       = v0;
        out[(size_t)n * OUTLD + tid + 128] = v1;
        X0h[(size_t)n * INDIM + tid]       = __float2half_rn(v0);
        X0h[(size_t)n * INDIM + tid + 128] = __float2half_rn(v1);
    }
}

// ======================= weight prep (all 3 layers, fp16 hi/lo) ============
__global__ void prep_w3(
    const float* __restrict__ W0, const float* __restrict__ b0,
    const float* __restrict__ W1, const float* __restrict__ b1,
    const float* __restrict__ W2, const float* __restrict__ b2,
    __half* __restrict__ Wh, __half* __restrict__ Wl,
    float* __restrict__ biasL)
{
    const int layer = blockIdx.y;
    const float* W = (layer == 0) ? W0 : (layer == 1) ? W1 : W2;
    const float* b = (layer == 0) ? b0 : (layer == 1) ? b1 : b2;
    const int Kin  = (layer == 0) ? INDIM : LDIM;

    __half* wh = Wh + (size_t)layer * WSTRIDE;
    __half* wl = Wl + (size_t)layer * WSTRIDE;

    int idx = blockIdx.x * blockDim.x + threadIdx.x;
    if (idx < 512 * Kin) {
        int r = idx / Kin, c = idx % Kin;
        float vl = W[(size_t)r * 2 * Kin + c];
        float vr = W[(size_t)r * 2 * Kin + Kin + c];
        float d  = vr - vl;

        __half h = __float2half_rn(vl);
        wh[(size_t)r * Kin + c] = h;
        wl[(size_t)r * Kin + c] = __float2half_rn(vl - __half2float(h));
        h = __float2half_rn(d);
        wh[(size_t)(512 + r) * Kin + c] = h;
        wl[(size_t)(512 + r) * Kin + c] = __float2half_rn(d - __half2float(h));
    }
    if (idx < 512) {
        biasL[layer * 1024 + idx]       = 0.0f;
        biasL[layer * 1024 + 512 + idx] = b[idx];
    }
}

// ---------------- aggregation: fp16 hmax reduction ------------------------
// max_k(a_k + c) == (max_k a_k) + c  (c constant per node),
// fp16 max is exact, fp32 add of two fp16 values is exact -> bit-identical
// to the previous add-then-max version, at 1/5 the instruction count.
// 256 threads = 4 nodes x 64 lanes; each lane owns 8 halves via uint4.
__global__ __launch_bounds__(256) void aggregate(
    const __half* __restrict__ D,
    const int*   __restrict__ src,
    __half* __restrict__ Xh,         // 4096 x 512
    float* __restrict__ out,         // 4096 x 1920
    int out_off)
{
    const int n   = blockIdx.x * 4 + (threadIdx.x >> 6);
    const int l64 = threadIdx.x & 63;      // 0..63, owns 8 halves

    const int* sp = src + n * KNBR;
    const size_t coff = (size_t)l64 * 8;

    // fp16 max over the 16 neighbors' A-rows
    int j0 = sp[0];
    uint4 aw = *(const uint4*)(D + (size_t)j0 * 1024 + coff);
    __half2 M0 = *(__half2*)&aw.x;
    __half2 M1 = *(__half2*)&aw.y;
    __half2 M2 = *(__half2*)&aw.z;
    __half2 M3 = *(__half2*)&aw.w;

    #pragma unroll
    for (int k = 1; k < KNBR; k++) {
        int j = sp[k];
        uint4 w = *(const uint4*)(D + (size_t)j * 1024 + coff);
        M0 = __hmax2(M0, *(__half2*)&w.x);
        M1 = __hmax2(M1, *(__half2*)&w.y);
        M2 = __hmax2(M2, *(__half2*)&w.z);
        M3 = __hmax2(M3, *(__half2*)&w.w);
    }

    // add C (exact fp32 adds of fp16 values), relu
    uint4 cw = *(const uint4*)(D + (size_t)n * 1024 + 512 + coff);
    float2 c0 = __half22float2(*(__half2*)&cw.x);
    float2 c1 = __half22float2(*(__half2*)&cw.y);
    float2 c2 = __half22float2(*(__half2*)&cw.z);
    float2 c3 = __half22float2(*(__half2*)&cw.w);
    float2 m0 = __half22float2(M0);
    float2 m1 = __half22float2(M1);
    float2 m2 = __half22float2(M2);
    float2 m3 = __half22float2(M3);

    float4 r0, r1;
    r0.x = fmaxf(m0.x + c0.x, 0.0f);  r0.y = fmaxf(m0.y + c0.y, 0.0f);
    r0.z = fmaxf(m1.x + c1.x, 0.0f);  r0.w = fmaxf(m1.y + c1.y, 0.0f);
    r1.x = fmaxf(m2.x + c2.x, 0.0f);  r1.y = fmaxf(m2.y + c2.y, 0.0f);
    r1.z = fmaxf(m3.x + c3.x, 0.0f);  r1.w = fmaxf(m3.y + c3.y, 0.0f);

    float* op = out + (size_t)n * OUTLD + out_off + l64 * 8;
    *(float4*)(op)     = r0;
    *(float4*)(op + 4) = r1;

    uint4 hx;
    *(__half2*)&hx.x = __floats2half2_rn(r0.x, r0.y);
    *(__half2*)&hx.y = __floats2half2_rn(r0.z, r0.w);
    *(__half2*)&hx.z = __floats2half2_rn(r1.x, r1.y);
    *(__half2*)&hx.w = __floats2half2_rn(r1.z, r1.w);
    *(uint4*)(Xh + (size_t)n * LDIM + l64 * 8) = hx;
}

// ---------------------------------------------------------------------------
extern "C" void kernel_launch(void* const* d_in, const int* in_sizes, int n_in,
                              void* d_out, int out_size)
{
    const float* rois   = (const float*)d_in[0];
    const float* pooled = (const float*)d_in[1];
    const int*   edge   = (const int*)  d_in[2];   // (2, 65536): row 0 = src
    const float* gW1    = (const float*)d_in[3];
    const float* gb1    = (const float*)d_in[4];
    const float* gW2    = (const float*)d_in[5];
    const float* gb2    = (const float*)d_in[6];
    const float* fcW[3] = {(const float*)d_in[7], (const float*)d_in[9],  (const float*)d_in[11]};
    const float* fcb[3] = {(const float*)d_in[8], (const float*)d_in[10], (const float*)d_in[12]};
    float* out = (float*)d_out;

    const int* src = edge;

    float *biasL;
    __half *D, *X0h, *Xh, *Wh, *Wl;
    cudaGetSymbolAddress((void**)&D,     g_D);
    cudaGetSymbolAddress((void**)&biasL, g_biasL);
    cudaGetSymbolAddress((void**)&X0h,   g_X0h);
    cudaGetSymbolAddress((void**)&Xh,    g_Xh);
    cudaGetSymbolAddress((void**)&Wh,    g_Wh);
    cudaGetSymbolAddress((void**)&Wl,    g_Wl);

    cudaFuncSetAttribute(gemm_mma, cudaFuncAttributeMaxDynamicSharedMemorySize, GEMM_SMEM);
    cudaFuncSetAttribute(geo_pre,  cudaFuncAttributeMaxDynamicSharedMemorySize, GEO_SMEM);

    // 1) fused geo prologue
    geo_pre<<<NNODES / GEO_NODES, 128, GEO_SMEM>>>(
        rois, pooled, gW1, gb1, gW2, gb2, out, X0h);

    // 2) all weight prep (independent of activations)
    prep_w3<<<dim3(1024, 3), 256>>>(
        fcW[0], fcb[0], fcW[1], fcb[1], fcW[2], fcb[2], Wh, Wl, biasL);

    // 3) three EdgeConv layers
    const int Kin[3]    = {INDIM, LDIM, LDIM};
    const int outOff[3] = {384, 384 + 512, 384 + 1024};

    for (int l = 0; l < 3; l++) {
        const __half* Ain = (l == 0) ? X0h : Xh;
        gemm_mma<<<dim3(1024 / 128, NNODES / 128), 256, GEMM_SMEM>>>(
            Ain, Wh + (size_t)l * WSTRIDE, Wl + (size_t)l * WSTRIDE,
            biasL + l * 1024, D, Kin[l]);

        aggregate<<<NNODES / 4, 256>>>(D, src, Xh, out, outOff[l]);
    }
}

// round 14
// speedup vs baseline: 1.7360x; 1.0021x over previous
#include <cuda_runtime.h>
#include <cuda_bf16.h>
#include <cuda_fp16.h>
#include <cstdint>

// Problem constants
#define NNODES 4096       // B*N = 8*512
#define KNBR   16
#define CPOOL  256
#define GDIM   128
#define INDIM  384        // CPOOL + GDIM
#define LDIM   512
#define OUTLD  1920       // 384 + 3*512
#define WSTRIDE (1024 * 512)

// ---------------- device scratch (no allocations allowed) ----------------
__device__ float g_biasL[3 * 1024];
__device__ __align__(16) __half g_D  [NNODES * 1024];
__device__ __align__(16) __half g_X0h[NNODES * INDIM];
__device__ __align__(16) __half g_Xh [NNODES * LDIM];
__device__ __align__(16) __half g_Wh [3 * WSTRIDE];
__device__ __align__(16) __half g_Wl [3 * WSTRIDE];

// ======================= helpers =======================
__device__ __forceinline__ uint32_t smem_u32(const void* p) {
    uint32_t a;
    asm("{ .reg .u64 t; cvta.to.shared.u64 t, %1; cvt.u32.u64 %0, t; }"
        : "=r"(a) : "l"(p));
    return a;
}
__device__ __forceinline__ uint32_t sw64(uint32_t o) {   // SW64 swizzle for 64B rows
    return o ^ ((o >> 3) & 0x30);
}
__device__ __forceinline__ void cp16(uint32_t dst, const void* src) {
    asm volatile("cp.async.cg.shared.global [%0], [%1], 16;" :: "r"(dst), "l"(src));
}
#define CP_COMMIT() asm volatile("cp.async.commit_group;" ::: "memory")
#define CP_WAIT(n)  asm volatile("cp.async.wait_group %0;" :: "n"(n) : "memory")

#define LDSM4(r, a) \
    asm volatile("ldmatrix.sync.aligned.m8n8.x4.shared.b16 {%0,%1,%2,%3}, [%4];" \
        : "=r"((r)[0]), "=r"((r)[1]), "=r"((r)[2]), "=r"((r)[3]) : "r"(a))

#define MMAF16(d, a, b0, b1) \
    asm volatile("mma.sync.aligned.m16n8k16.row.col.f32.f16.f16.f32 " \
        "{%0,%1,%2,%3}, {%4,%5,%6,%7}, {%8,%9}, {%0,%1,%2,%3};" \
        : "+f"((d)[0]), "+f"((d)[1]), "+f"((d)[2]), "+f"((d)[3]) \
        : "r"((a)[0]), "r"((a)[1]), "r"((a)[2]), "r"((a)[3]), "r"(b0), "r"(b1))

// ======================= mma.sync GEMM (fp16, 2-pass) ======================
// D(4096 x 1024, fp16) = X(4096 x Kin) @ W(1024 x Kin)^T + bias
// A = activations rounded to fp16; W split into fp16 hi + lo (exact).
// D = A*Wh + A*Wl, fp32 accumulation, fp16 store.
// CTA tile 128x128, BK=32, 8 warps (warp tile 32x64), cp.async double buffer.
#define ARR_BYTES (128 * 64)                // 8192
#define STG_BYTES (3 * ARR_BYTES)           // 24576
#define GEMM_SMEM (2 * STG_BYTES)           // 49152

__global__ __launch_bounds__(256) void gemm_mma(
    const __half* __restrict__ A,
    const __half* __restrict__ Bh, const __half* __restrict__ Bl,
    const float* __restrict__ bias,
    __half* __restrict__ C,     // ldc = 1024, fp16
    int Kin)
{
    extern __shared__ char smem[];
    const uint32_t sb  = smem_u32(smem);
    const int tid  = threadIdx.x;
    const int lane = tid & 31;
    const int wid  = tid >> 5;
    const int bm   = blockIdx.y * 128;
    const int bn   = blockIdx.x * 128;
    const int m0   = (wid & 3) * 32;     // warp m-offset in tile
    const int n0   = (wid >> 2) * 64;    // warp n-offset in tile

    // cp.async chunk mapping: 512 chunks of 16B per array, 2 per thread
    const int r0c = tid >> 2;            // rows 0..63
    const int s0c = tid & 3;             // seg 0..3
    const int r1c = (tid + 256) >> 2;    // rows 64..127

    const __half* gsrc[3] = { A, Bh, Bl };
    const int grow0[3] = { bm, bn, bn };

    uint32_t soff0[3], soff1[3];
    #pragma unroll
    for (int a = 0; a < 3; a++) {
        soff0[a] = a * ARR_BYTES + sw64((uint32_t)(r0c * 64 + s0c * 16));
        soff1[a] = a * ARR_BYTES + sw64((uint32_t)(r1c * 64 + s0c * 16));
    }

    const int nk = Kin / 32;

    // ---- issue stage 0 ----
    {
        const uint32_t bufb = sb;
        #pragma unroll
        for (int a = 0; a < 3; a++) {
            cp16(bufb + soff0[a], gsrc[a] + (size_t)(grow0[a] + r0c) * Kin + s0c * 8);
            cp16(bufb + soff1[a], gsrc[a] + (size_t)(grow0[a] + r1c) * Kin + s0c * 8);
        }
        CP_COMMIT();
    }

    float acc[2][8][4];
    #pragma unroll
    for (int i = 0; i < 2; i++)
        #pragma unroll
        for (int j = 0; j < 8; j++)
            #pragma unroll
            for (int q = 0; q < 4; q++)
                acc[i][j][q] = 0.0f;

    // ldmatrix per-lane address components
    const int a_row = lane & 15;
    const int a_kh  = (lane >> 4) & 1;
    const int b_row = ((lane >> 4) << 3) + (lane & 7);
    const int b_kh  = (lane >> 3) & 1;

    for (int s = 0; s < nk; s++) {
        const uint32_t bufb = sb + (uint32_t)(s & 1) * STG_BYTES;

        if (s + 1 < nk) {
            const uint32_t nb = sb + (uint32_t)((s + 1) & 1) * STG_BYTES;
            const int kb = (s + 1) * 32;
            #pragma unroll
            for (int a = 0; a < 3; a++) {
                cp16(nb + soff0[a], gsrc[a] + (size_t)(grow0[a] + r0c) * Kin + kb + s0c * 8);
                cp16(nb + soff1[a], gsrc[a] + (size_t)(grow0[a] + r1c) * Kin + kb + s0c * 8);
            }
            CP_COMMIT();
            CP_WAIT(1);
        } else {
            CP_WAIT(0);
        }
        __syncthreads();

        #pragma unroll
        for (int kk = 0; kk < 2; kk++) {
            uint32_t fa[2][4];
            #pragma unroll
            for (int mt = 0; mt < 2; mt++) {
                const uint32_t off =
                    sw64((uint32_t)((m0 + mt * 16 + a_row) * 64 + kk * 32 + a_kh * 16));
                LDSM4(fa[mt], bufb + 0 * ARR_BYTES + off);
            }
            uint32_t fbh[4][4], fbl[4][4];
            #pragma unroll
            for (int nt = 0; nt < 4; nt++) {
                const uint32_t off =
                    sw64((uint32_t)((n0 + nt * 16 + b_row) * 64 + kk * 32 + b_kh * 16));
                LDSM4(fbh[nt], bufb + 1 * ARR_BYTES + off);
                LDSM4(fbl[nt], bufb + 2 * ARR_BYTES + off);
            }
            #pragma unroll
            for (int mt = 0; mt < 2; mt++) {
                #pragma unroll
                for (int ni = 0; ni < 8; ni++) {
                    const uint32_t bh0 = fbh[ni >> 1][(ni & 1) * 2];
                    const uint32_t bh1 = fbh[ni >> 1][(ni & 1) * 2 + 1];
                    const uint32_t bl0 = fbl[ni >> 1][(ni & 1) * 2];
                    const uint32_t bl1 = fbl[ni >> 1][(ni & 1) * 2 + 1];
                    MMAF16(acc[mt][ni], fa[mt], bh0, bh1);
                    MMAF16(acc[mt][ni], fa[mt], bl0, bl1);
                }
            }
        }
        __syncthreads();
    }

    // ---- epilogue: write D (fp16) with bias ----
    #pragma unroll
    for (int mt = 0; mt < 2; mt++) {
        const int r = bm + m0 + mt * 16 + (lane >> 2);
        #pragma unroll
        for (int ni = 0; ni < 8; ni++) {
            const int col = bn + n0 + ni * 8 + (lane & 3) * 2;
            const float b0 = bias[col], b1 = bias[col + 1];
            __half2 v0 = __floats2half2_rn(acc[mt][ni][0] + b0, acc[mt][ni][1] + b1);
            __half2 v1 = __floats2half2_rn(acc[mt][ni][2] + b0, acc[mt][ni][3] + b1);
            *(__half2*)(C + (size_t)r * 1024 + col)       = v0;
            *(__half2*)(C + (size_t)(r + 8) * 1024 + col) = v1;
        }
    }
}

// ======================= fused geo prologue =======================
#define GEO_NODES 16
#define GEO_W2T   0
#define GEO_W1    (128 * 129)
#define GEO_B1    (GEO_W1 + 896)
#define GEO_B2    (GEO_B1 + 128)
#define GEO_ROI   (GEO_B2 + 128)
#define GEO_H     (GEO_ROI + 128)
#define GEO_SMEMF (GEO_H + GEO_NODES * 132)
#define GEO_SMEM  (GEO_SMEMF * 4)

__global__ __launch_bounds__(128) void geo_pre(
    const float* __restrict__ rois,
    const float* __restrict__ pooled,
    const float* __restrict__ gW1, const float* __restrict__ gb1,
    const float* __restrict__ gW2, const float* __restrict__ gb2,
    float* __restrict__ out,
    __half* __restrict__ X0h)
{
    extern __shared__ float s[];
    const int tid = threadIdx.x;
    const int n0  = blockIdx.x * GEO_NODES;

    for (int i = tid; i < 128 * 128; i += 128) {
        int r = i >> 7, c = i & 127;
        s[GEO_W2T + c * 129 + r] = gW2[i];
    }
    for (int i = tid; i < 896; i += 128) s[GEO_W1 + i] = gW1[i];
    s[GEO_B1 + tid] = gb1[tid];
    s[GEO_B2 + tid] = gb2[tid];
    if (tid < GEO_NODES * 7) {
        int node = tid / 7, j = tid - node * 7;
        s[GEO_ROI + node * 8 + j] = rois[(size_t)(n0 + node) * 7 + j];
    }
    __syncthreads();

    #pragma unroll
    for (int node = 0; node < GEO_NODES; node++) {
        float a = s[GEO_B1 + tid];
        #pragma unroll
        for (int j = 0; j < 7; j++)
            a = fmaf(s[GEO_W1 + tid * 7 + j], s[GEO_ROI + node * 8 + j], a);
        s[GEO_H + node * 132 + tid] = fmaxf(a, 0.0f);
    }
    __syncthreads();

    float acc[GEO_NODES];
    #pragma unroll
    for (int node = 0; node < GEO_NODES; node++) acc[node] = s[GEO_B2 + tid];

    #pragma unroll 8
    for (int j = 0; j < 128; j += 4) {
        const float w0 = s[GEO_W2T + (j + 0) * 129 + tid];
        const float w1 = s[GEO_W2T + (j + 1) * 129 + tid];
        const float w2 = s[GEO_W2T + (j + 2) * 129 + tid];
        const float w3 = s[GEO_W2T + (j + 3) * 129 + tid];
        #pragma unroll
        for (int node = 0; node < GEO_NODES; node++) {
            float4 h = *(const float4*)&s[GEO_H + node * 132 + j];
            float a = acc[node];
            a = fmaf(w0, h.x, a);
            a = fmaf(w1, h.y, a);
            a = fmaf(w2, h.z, a);
            a = fmaf(w3, h.w, a);
            acc[node] = a;
        }
    }

    #pragma unroll
    for (int node = 0; node < GEO_NODES; node++) {
        const int n = n0 + node;
        const float g = fmaxf(acc[node], 0.0f);
        out[(size_t)n * OUTLD + CPOOL + tid] = g;
        X0h[(size_t)n * INDIM + CPOOL + tid] = __float2half_rn(g);

        const float v0 = pooled[(size_t)n * CPOOL + tid];
        const float v1 = pooled[(size_t)n * CPOOL + tid + 128];
        out[(size_t)n * OUTLD + tid]       = v0;
        out[(size_t)n * OUTLD + tid + 128] = v1;
        X0h[(size_t)n * INDIM + tid]       = __float2half_rn(v0);
        X0h[(size_t)n * INDIM + tid + 128] = __float2half_rn(v1);
    }
}

// ======================= weight prep (all 3 layers, fp16 hi/lo) ============
__global__ void prep_w3(
    const float* __restrict__ W0, const float* __restrict__ b0,
    const float* __restrict__ W1, const float* __restrict__ b1,
    const float* __restrict__ W2, const float* __restrict__ b2,
    __half* __restrict__ Wh, __half* __restrict__ Wl,
    float* __restrict__ biasL)
{
    const int layer = blockIdx.y;
    const float* W = (layer == 0) ? W0 : (layer == 1) ? W1 : W2;
    const float* b = (layer == 0) ? b0 : (layer == 1) ? b1 : b2;
    const int Kin  = (layer == 0) ? INDIM : LDIM;

    __half* wh = Wh + (size_t)layer * WSTRIDE;
    __half* wl = Wl + (size_t)layer * WSTRIDE;

    int idx = blockIdx.x * blockDim.x + threadIdx.x;
    if (idx < 512 * Kin) {
        int r = idx / Kin, c = idx % Kin;
        float vl = W[(size_t)r * 2 * Kin + c];
        float vr = W[(size_t)r * 2 * Kin + Kin + c];
        float d  = vr - vl;

        __half h = __float2half_rn(vl);
        wh[(size_t)r * Kin + c] = h;
        wl[(size_t)r * Kin + c] = __float2half_rn(vl - __half2float(h));
        h = __float2half_rn(d);
        wh[(size_t)(512 + r) * Kin + c] = h;
        wl[(size_t)(512 + r) * Kin + c] = __float2half_rn(d - __half2float(h));
    }
    if (idx < 512) {
        biasL[layer * 1024 + idx]       = 0.0f;
        biasL[layer * 1024 + 512 + idx] = b[idx];
    }
}

// ---------------- aggregation: fp16 hmax reduction, 4-way batched ---------
// max_k(a_k + c) == (max_k a_k) + c; fp16 max exact; fp32 add of fp16 exact.
// Neighbors processed in batches of 4 with all 4 uint4 loads issued before
// the reduction ops -> MLP ~4+ instead of ~2 (was latency-bound at regs=32).
__global__ __launch_bounds__(256) void aggregate(
    const __half* __restrict__ D,
    const int*   __restrict__ src,
    __half* __restrict__ Xh,         // 4096 x 512
    float* __restrict__ out,         // 4096 x 1920
    int out_off, int write_xh)
{
    const int n   = blockIdx.x * 4 + (threadIdx.x >> 6);
    const int l64 = threadIdx.x & 63;      // 0..63, owns 8 halves

    const size_t coff = (size_t)l64 * 8;

    // preload all 16 neighbor indices
    int js[KNBR];
    #pragma unroll
    for (int k = 0; k < KNBR; k++) js[k] = src[n * KNBR + k];

    __half2 M0, M1, M2, M3;
    {
        uint4 w = *(const uint4*)(D + (size_t)js[0] * 1024 + coff);
        M0 = *(__half2*)&w.x;  M1 = *(__half2*)&w.y;
        M2 = *(__half2*)&w.z;  M3 = *(__half2*)&w.w;
        uint4 w1 = *(const uint4*)(D + (size_t)js[1] * 1024 + coff);
        uint4 w2 = *(const uint4*)(D + (size_t)js[2] * 1024 + coff);
        uint4 w3 = *(const uint4*)(D + (size_t)js[3] * 1024 + coff);
        M0 = __hmax2(M0, *(__half2*)&w1.x); M1 = __hmax2(M1, *(__half2*)&w1.y);
        M2 = __hmax2(M2, *(__half2*)&w1.z); M3 = __hmax2(M3, *(__half2*)&w1.w);
        M0 = __hmax2(M0, *(__half2*)&w2.x); M1 = __hmax2(M1, *(__half2*)&w2.y);
        M2 = __hmax2(M2, *(__half2*)&w2.z); M3 = __hmax2(M3, *(__half2*)&w2.w);
        M0 = __hmax2(M0, *(__half2*)&w3.x); M1 = __hmax2(M1, *(__half2*)&w3.y);
        M2 = __hmax2(M2, *(__half2*)&w3.z); M3 = __hmax2(M3, *(__half2*)&w3.w);
    }
    #pragma unroll
    for (int k0 = 4; k0 < KNBR; k0 += 4) {
        uint4 w0 = *(const uint4*)(D + (size_t)js[k0 + 0] * 1024 + coff);
        uint4 w1 = *(const uint4*)(D + (size_t)js[k0 + 1] * 1024 + coff);
        uint4 w2 = *(const uint4*)(D + (size_t)js[k0 + 2] * 1024 + coff);
        uint4 w3 = *(const uint4*)(D + (size_t)js[k0 + 3] * 1024 + coff);
        M0 = __hmax2(M0, *(__half2*)&w0.x); M1 = __hmax2(M1, *(__half2*)&w0.y);
        M2 = __hmax2(M2, *(__half2*)&w0.z); M3 = __hmax2(M3, *(__half2*)&w0.w);
        M0 = __hmax2(M0, *(__half2*)&w1.x); M1 = __hmax2(M1, *(__half2*)&w1.y);
        M2 = __hmax2(M2, *(__half2*)&w1.z); M3 = __hmax2(M3, *(__half2*)&w1.w);
        M0 = __hmax2(M0, *(__half2*)&w2.x); M1 = __hmax2(M1, *(__half2*)&w2.y);
        M2 = __hmax2(M2, *(__half2*)&w2.z); M3 = __hmax2(M3, *(__half2*)&w2.w);
        M0 = __hmax2(M0, *(__half2*)&w3.x); M1 = __hmax2(M1, *(__half2*)&w3.y);
        M2 = __hmax2(M2, *(__half2*)&w3.z); M3 = __hmax2(M3, *(__half2*)&w3.w);
    }

    // add C (exact fp32 adds of fp16 values), relu
    uint4 cw = *(const uint4*)(D + (size_t)n * 1024 + 512 + coff);
    float2 c0 = __half22float2(*(__half2*)&cw.x);
    float2 c1 = __half22float2(*(__half2*)&cw.y);
    float2 c2 = __half22float2(*(__half2*)&cw.z);
    float2 c3 = __half22float2(*(__half2*)&cw.w);
    float2 m0 = __half22float2(M0);
    float2 m1 = __half22float2(M1);
    float2 m2 = __half22float2(M2);
    float2 m3 = __half22float2(M3);

    float4 r0, r1;
    r0.x = fmaxf(m0.x + c0.x, 0.0f);  r0.y = fmaxf(m0.y + c0.y, 0.0f);
    r0.z = fmaxf(m1.x + c1.x, 0.0f);  r0.w = fmaxf(m1.y + c1.y, 0.0f);
    r1.x = fmaxf(m2.x + c2.x, 0.0f);  r1.y = fmaxf(m2.y + c2.y, 0.0f);
    r1.z = fmaxf(m3.x + c3.x, 0.0f);  r1.w = fmaxf(m3.y + c3.y, 0.0f);

    float* op = out + (size_t)n * OUTLD + out_off + l64 * 8;
    *(float4*)(op)     = r0;
    *(float4*)(op + 4) = r1;

    if (write_xh) {
        uint4 hx;
        *(__half2*)&hx.x = __floats2half2_rn(r0.x, r0.y);
        *(__half2*)&hx.y = __floats2half2_rn(r0.z, r0.w);
        *(__half2*)&hx.z = __floats2half2_rn(r1.x, r1.y);
        *(__half2*)&hx.w = __floats2half2_rn(r1.z, r1.w);
        *(uint4*)(Xh + (size_t)n * LDIM + l64 * 8) = hx;
    }
}

// ---------------------------------------------------------------------------
extern "C" void kernel_launch(void* const* d_in, const int* in_sizes, int n_in,
                              void* d_out, int out_size)
{
    const float* rois   = (const float*)d_in[0];
    const float* pooled = (const float*)d_in[1];
    const int*   edge   = (const int*)  d_in[2];   // (2, 65536): row 0 = src
    const float* gW1    = (const float*)d_in[3];
    const float* gb1    = (const float*)d_in[4];
    const float* gW2    = (const float*)d_in[5];
    const float* gb2    = (const float*)d_in[6];
    const float* fcW[3] = {(const float*)d_in[7], (const float*)d_in[9],  (const float*)d_in[11]};
    const float* fcb[3] = {(const float*)d_in[8], (const float*)d_in[10], (const float*)d_in[12]};
    float* out = (float*)d_out;

    const int* src = edge;

    float *biasL;
    __half *D, *X0h, *Xh, *Wh, *Wl;
    cudaGetSymbolAddress((void**)&D,     g_D);
    cudaGetSymbolAddress((void**)&biasL, g_biasL);
    cudaGetSymbolAddress((void**)&X0h,   g_X0h);
    cudaGetSymbolAddress((void**)&Xh,    g_Xh);
    cudaGetSymbolAddress((void**)&Wh,    g_Wh);
    cudaGetSymbolAddress((void**)&Wl,    g_Wl);

    cudaFuncSetAttribute(gemm_mma, cudaFuncAttributeMaxDynamicSharedMemorySize, GEMM_SMEM);
    cudaFuncSetAttribute(geo_pre,  cudaFuncAttributeMaxDynamicSharedMemorySize, GEO_SMEM);

    // 1) fused geo prologue
    geo_pre<<<NNODES / GEO_NODES, 128, GEO_SMEM>>>(
        rois, pooled, gW1, gb1, gW2, gb2, out, X0h);

    // 2) all weight prep (independent of activations)
    prep_w3<<<dim3(1024, 3), 256>>>(
        fcW[0], fcb[0], fcW[1], fcb[1], fcW[2], fcb[2], Wh, Wl, biasL);

    // 3) three EdgeConv layers
    const int Kin[3]    = {INDIM, LDIM, LDIM};
    const int outOff[3] = {384, 384 + 512, 384 + 1024};

    for (int l = 0; l < 3; l++) {
        const __half* Ain = (l == 0) ? X0h : Xh;
        gemm_mma<<<dim3(1024 / 128, NNODES / 128), 256, GEMM_SMEM>>>(
            Ain, Wh + (size_t)l * WSTRIDE, Wl + (size_t)l * WSTRIDE,
            biasL + l * 1024, D, Kin[l]);

        aggregate<<<NNODES / 4, 256>>>(D, src, Xh, out, outOff[l], l < 2 ? 1 : 0);
    }
}

// round 15
// speedup vs baseline: 1.7425x; 1.0037x over previous
#include <cuda_runtime.h>
#include <cuda_bf16.h>
#include <cuda_fp16.h>
#include <cstdint>

// Problem constants
#define NNODES 4096       // B*N = 8*512
#define KNBR   16
#define CPOOL  256
#define GDIM   128
#define INDIM  384        // CPOOL + GDIM
#define LDIM   512
#define OUTLD  1920       // 384 + 3*512
#define WSTRIDE (1024 * 512)

// ---------------- device scratch (no allocations allowed) ----------------
__device__ float g_biasL[3 * 1024];
__device__ __align__(16) __half g_D  [NNODES * 1024];
__device__ __align__(16) __half g_X0h[NNODES * INDIM];
__device__ __align__(16) __half g_Xh [NNODES * LDIM];
__device__ __align__(16) __half g_Wh [3 * WSTRIDE];
__device__ __align__(16) __half g_Wl [3 * WSTRIDE];

// ======================= helpers =======================
__device__ __forceinline__ uint32_t smem_u32(const void* p) {
    uint32_t a;
    asm("{ .reg .u64 t; cvta.to.shared.u64 t, %1; cvt.u32.u64 %0, t; }"
        : "=r"(a) : "l"(p));
    return a;
}
__device__ __forceinline__ uint32_t sw64(uint32_t o) {   // SW64 swizzle for 64B rows
    return o ^ ((o >> 3) & 0x30);
}
__device__ __forceinline__ void cp16(uint32_t dst, const void* src) {
    asm volatile("cp.async.cg.shared.global [%0], [%1], 16;" :: "r"(dst), "l"(src));
}
#define CP_COMMIT() asm volatile("cp.async.commit_group;" ::: "memory")
#define CP_WAIT(n)  asm volatile("cp.async.wait_group %0;" :: "n"(n) : "memory")

#define LDSM4(r, a) \
    asm volatile("ldmatrix.sync.aligned.m8n8.x4.shared.b16 {%0,%1,%2,%3}, [%4];" \
        : "=r"((r)[0]), "=r"((r)[1]), "=r"((r)[2]), "=r"((r)[3]) : "r"(a))

#define MMAF16(d, a, b0, b1) \
    asm volatile("mma.sync.aligned.m16n8k16.row.col.f32.f16.f16.f32 " \
        "{%0,%1,%2,%3}, {%4,%5,%6,%7}, {%8,%9}, {%0,%1,%2,%3};" \
        : "+f"((d)[0]), "+f"((d)[1]), "+f"((d)[2]), "+f"((d)[3]) \
        : "r"((a)[0]), "r"((a)[1]), "r"((a)[2]), "r"((a)[3]), "r"(b0), "r"(b1))

// forced 16B non-coherent load (volatile: cannot be sunk/reordered by ptxas)
#define LDG16(v, ptr) \
    asm volatile("ld.global.nc.v4.u32 {%0,%1,%2,%3}, [%4];" \
        : "=r"((v).x), "=r"((v).y), "=r"((v).z), "=r"((v).w) : "l"(ptr))

// ======================= mma.sync GEMM (fp16, 2-pass) ======================
// D(4096 x 1024, fp16) = X(4096 x Kin) @ W(1024 x Kin)^T + bias
// A = activations rounded to fp16; W split into fp16 hi + lo (exact).
// D = A*Wh + A*Wl, fp32 accumulation, fp16 store.
// CTA tile 128x128, BK=32, 8 warps (warp tile 32x64), cp.async double buffer.
#define ARR_BYTES (128 * 64)                // 8192
#define STG_BYTES (3 * ARR_BYTES)           // 24576
#define GEMM_SMEM (2 * STG_BYTES)           // 49152

__global__ __launch_bounds__(256) void gemm_mma(
    const __half* __restrict__ A,
    const __half* __restrict__ Bh, const __half* __restrict__ Bl,
    const float* __restrict__ bias,
    __half* __restrict__ C,     // ldc = 1024, fp16
    int Kin)
{
    extern __shared__ char smem[];
    const uint32_t sb  = smem_u32(smem);
    const int tid  = threadIdx.x;
    const int lane = tid & 31;
    const int wid  = tid >> 5;
    const int bm   = blockIdx.y * 128;
    const int bn   = blockIdx.x * 128;
    const int m0   = (wid & 3) * 32;     // warp m-offset in tile
    const int n0   = (wid >> 2) * 64;    // warp n-offset in tile

    // cp.async chunk mapping: 512 chunks of 16B per array, 2 per thread
    const int r0c = tid >> 2;            // rows 0..63
    const int s0c = tid & 3;             // seg 0..3
    const int r1c = (tid + 256) >> 2;    // rows 64..127

    const __half* gsrc[3] = { A, Bh, Bl };
    const int grow0[3] = { bm, bn, bn };

    uint32_t soff0[3], soff1[3];
    #pragma unroll
    for (int a = 0; a < 3; a++) {
        soff0[a] = a * ARR_BYTES + sw64((uint32_t)(r0c * 64 + s0c * 16));
        soff1[a] = a * ARR_BYTES + sw64((uint32_t)(r1c * 64 + s0c * 16));
    }

    const int nk = Kin / 32;

    // ---- issue stage 0 ----
    {
        const uint32_t bufb = sb;
        #pragma unroll
        for (int a = 0; a < 3; a++) {
            cp16(bufb + soff0[a], gsrc[a] + (size_t)(grow0[a] + r0c) * Kin + s0c * 8);
            cp16(bufb + soff1[a], gsrc[a] + (size_t)(grow0[a] + r1c) * Kin + s0c * 8);
        }
        CP_COMMIT();
    }

    float acc[2][8][4];
    #pragma unroll
    for (int i = 0; i < 2; i++)
        #pragma unroll
        for (int j = 0; j < 8; j++)
            #pragma unroll
            for (int q = 0; q < 4; q++)
                acc[i][j][q] = 0.0f;

    // ldmatrix per-lane address components
    const int a_row = lane & 15;
    const int a_kh  = (lane >> 4) & 1;
    const int b_row = ((lane >> 4) << 3) + (lane & 7);
    const int b_kh  = (lane >> 3) & 1;

    for (int s = 0; s < nk; s++) {
        const uint32_t bufb = sb + (uint32_t)(s & 1) * STG_BYTES;

        if (s + 1 < nk) {
            const uint32_t nb = sb + (uint32_t)((s + 1) & 1) * STG_BYTES;
            const int kb = (s + 1) * 32;
            #pragma unroll
            for (int a = 0; a < 3; a++) {
                cp16(nb + soff0[a], gsrc[a] + (size_t)(grow0[a] + r0c) * Kin + kb + s0c * 8);
                cp16(nb + soff1[a], gsrc[a] + (size_t)(grow0[a] + r1c) * Kin + kb + s0c * 8);
            }
            CP_COMMIT();
            CP_WAIT(1);
        } else {
            CP_WAIT(0);
        }
        __syncthreads();

        #pragma unroll
        for (int kk = 0; kk < 2; kk++) {
            uint32_t fa[2][4];
            #pragma unroll
            for (int mt = 0; mt < 2; mt++) {
                const uint32_t off =
                    sw64((uint32_t)((m0 + mt * 16 + a_row) * 64 + kk * 32 + a_kh * 16));
                LDSM4(fa[mt], bufb + 0 * ARR_BYTES + off);
            }
            uint32_t fbh[4][4], fbl[4][4];
            #pragma unroll
            for (int nt = 0; nt < 4; nt++) {
                const uint32_t off =
                    sw64((uint32_t)((n0 + nt * 16 + b_row) * 64 + kk * 32 + b_kh * 16));
                LDSM4(fbh[nt], bufb + 1 * ARR_BYTES + off);
                LDSM4(fbl[nt], bufb + 2 * ARR_BYTES + off);
            }
            #pragma unroll
            for (int mt = 0; mt < 2; mt++) {
                #pragma unroll
                for (int ni = 0; ni < 8; ni++) {
                    const uint32_t bh0 = fbh[ni >> 1][(ni & 1) * 2];
                    const uint32_t bh1 = fbh[ni >> 1][(ni & 1) * 2 + 1];
                    const uint32_t bl0 = fbl[ni >> 1][(ni & 1) * 2];
                    const uint32_t bl1 = fbl[ni >> 1][(ni & 1) * 2 + 1];
                    MMAF16(acc[mt][ni], fa[mt], bh0, bh1);
                    MMAF16(acc[mt][ni], fa[mt], bl0, bl1);
                }
            }
        }
        __syncthreads();
    }

    // ---- epilogue: write D (fp16) with bias ----
    #pragma unroll
    for (int mt = 0; mt < 2; mt++) {
        const int r = bm + m0 + mt * 16 + (lane >> 2);
        #pragma unroll
        for (int ni = 0; ni < 8; ni++) {
            const int col = bn + n0 + ni * 8 + (lane & 3) * 2;
            const float b0 = bias[col], b1 = bias[col + 1];
            __half2 v0 = __floats2half2_rn(acc[mt][ni][0] + b0, acc[mt][ni][1] + b1);
            __half2 v1 = __floats2half2_rn(acc[mt][ni][2] + b0, acc[mt][ni][3] + b1);
            *(__half2*)(C + (size_t)r * 1024 + col)       = v0;
            *(__half2*)(C + (size_t)(r + 8) * 1024 + col) = v1;
        }
    }
}

// ======================= fused geo prologue =======================
#define GEO_NODES 16
#define GEO_W2T   0
#define GEO_W1    (128 * 129)
#define GEO_B1    (GEO_W1 + 896)
#define GEO_B2    (GEO_B1 + 128)
#define GEO_ROI   (GEO_B2 + 128)
#define GEO_H     (GEO_ROI + 128)
#define GEO_SMEMF (GEO_H + GEO_NODES * 132)
#define GEO_SMEM  (GEO_SMEMF * 4)

__global__ __launch_bounds__(128) void geo_pre(
    const float* __restrict__ rois,
    const float* __restrict__ pooled,
    const float* __restrict__ gW1, const float* __restrict__ gb1,
    const float* __restrict__ gW2, const float* __restrict__ gb2,
    float* __restrict__ out,
    __half* __restrict__ X0h)
{
    extern __shared__ float s[];
    const int tid = threadIdx.x;
    const int n0  = blockIdx.x * GEO_NODES;

    for (int i = tid; i < 128 * 128; i += 128) {
        int r = i >> 7, c = i & 127;
        s[GEO_W2T + c * 129 + r] = gW2[i];
    }
    for (int i = tid; i < 896; i += 128) s[GEO_W1 + i] = gW1[i];
    s[GEO_B1 + tid] = gb1[tid];
    s[GEO_B2 + tid] = gb2[tid];
    if (tid < GEO_NODES * 7) {
        int node = tid / 7, j = tid - node * 7;
        s[GEO_ROI + node * 8 + j] = rois[(size_t)(n0 + node) * 7 + j];
    }
    __syncthreads();

    #pragma unroll
    for (int node = 0; node < GEO_NODES; node++) {
        float a = s[GEO_B1 + tid];
        #pragma unroll
        for (int j = 0; j < 7; j++)
            a = fmaf(s[GEO_W1 + tid * 7 + j], s[GEO_ROI + node * 8 + j], a);
        s[GEO_H + node * 132 + tid] = fmaxf(a, 0.0f);
    }
    __syncthreads();

    float acc[GEO_NODES];
    #pragma unroll
    for (int node = 0; node < GEO_NODES; node++) acc[node] = s[GEO_B2 + tid];

    #pragma unroll 8
    for (int j = 0; j < 128; j += 4) {
        const float w0 = s[GEO_W2T + (j + 0) * 129 + tid];
        const float w1 = s[GEO_W2T + (j + 1) * 129 + tid];
        const float w2 = s[GEO_W2T + (j + 2) * 129 + tid];
        const float w3 = s[GEO_W2T + (j + 3) * 129 + tid];
        #pragma unroll
        for (int node = 0; node < GEO_NODES; node++) {
            float4 h = *(const float4*)&s[GEO_H + node * 132 + j];
            float a = acc[node];
            a = fmaf(w0, h.x, a);
            a = fmaf(w1, h.y, a);
            a = fmaf(w2, h.z, a);
            a = fmaf(w3, h.w, a);
            acc[node] = a;
        }
    }

    #pragma unroll
    for (int node = 0; node < GEO_NODES; node++) {
        const int n = n0 + node;
        const float g = fmaxf(acc[node], 0.0f);
        out[(size_t)n * OUTLD + CPOOL + tid] = g;
        X0h[(size_t)n * INDIM + CPOOL + tid] = __float2half_rn(g);

        const float v0 = pooled[(size_t)n * CPOOL + tid];
        const float v1 = pooled[(size_t)n * CPOOL + tid + 128];
        out[(size_t)n * OUTLD + tid]       = v0;
        out[(size_t)n * OUTLD + tid + 128] = v1;
        X0h[(size_t)n * INDIM + tid]       = __float2half_rn(v0);
        X0h[(size_t)n * INDIM + tid + 128] = __float2half_rn(v1);
    }
}

// ======================= weight prep (all 3 layers, fp16 hi/lo) ============
__global__ void prep_w3(
    const float* __restrict__ W0, const float* __restrict__ b0,
    const float* __restrict__ W1, const float* __restrict__ b1,
    const float* __restrict__ W2, const float* __restrict__ b2,
    __half* __restrict__ Wh, __half* __restrict__ Wl,
    float* __restrict__ biasL)
{
    const int layer = blockIdx.y;
    const float* W = (layer == 0) ? W0 : (layer == 1) ? W1 : W2;
    const float* b = (layer == 0) ? b0 : (layer == 1) ? b1 : b2;
    const int Kin  = (layer == 0) ? INDIM : LDIM;

    __half* wh = Wh + (size_t)layer * WSTRIDE;
    __half* wl = Wl + (size_t)layer * WSTRIDE;

    int idx = blockIdx.x * blockDim.x + threadIdx.x;
    if (idx < 512 * Kin) {
        int r = idx / Kin, c = idx % Kin;
        float vl = W[(size_t)r * 2 * Kin + c];
        float vr = W[(size_t)r * 2 * Kin + Kin + c];
        float d  = vr - vl;

        __half h = __float2half_rn(vl);
        wh[(size_t)r * Kin + c] = h;
        wl[(size_t)r * Kin + c] = __float2half_rn(vl - __half2float(h));
        h = __float2half_rn(d);
        wh[(size_t)(512 + r) * Kin + c] = h;
        wl[(size_t)(512 + r) * Kin + c] = __float2half_rn(d - __half2float(h));
    }
    if (idx < 512) {
        biasL[layer * 1024 + idx]       = 0.0f;
        biasL[layer * 1024 + 512 + idx] = b[idx];
    }
}

// ---------------- aggregation: fp16 hmax, asm-forced 4-batch loads --------
// max_k(a_k + c) == (max_k a_k) + c; fp16 max exact; fp32 add of fp16 exact.
// Loads issued in groups of 4 via asm volatile ld.global.nc.v4 (ptxas cannot
// sink/reorder volatile asm), forcing ~4 loads in flight.
__global__ __launch_bounds__(256) void aggregate(
    const __half* __restrict__ D,
    const int*   __restrict__ src,
    __half* __restrict__ Xh,         // 4096 x 512
    float* __restrict__ out,         // 4096 x 1920
    int out_off, int write_xh)
{
    const int n   = blockIdx.x * 4 + (threadIdx.x >> 6);
    const int l64 = threadIdx.x & 63;      // 0..63, owns 8 halves

    const int* sp = src + n * KNBR;
    const size_t coff = (size_t)l64 * 8;

    __half2 M0, M1, M2, M3;
    {
        uint4 w0, w1, w2, w3;
        LDG16(w0, D + (size_t)sp[0] * 1024 + coff);
        LDG16(w1, D + (size_t)sp[1] * 1024 + coff);
        LDG16(w2, D + (size_t)sp[2] * 1024 + coff);
        LDG16(w3, D + (size_t)sp[3] * 1024 + coff);
        M0 = *(__half2*)&w0.x;  M1 = *(__half2*)&w0.y;
        M2 = *(__half2*)&w0.z;  M3 = *(__half2*)&w0.w;
        M0 = __hmax2(M0, *(__half2*)&w1.x); M1 = __hmax2(M1, *(__half2*)&w1.y);
        M2 = __hmax2(M2, *(__half2*)&w1.z); M3 = __hmax2(M3, *(__half2*)&w1.w);
        M0 = __hmax2(M0, *(__half2*)&w2.x); M1 = __hmax2(M1, *(__half2*)&w2.y);
        M2 = __hmax2(M2, *(__half2*)&w2.z); M3 = __hmax2(M3, *(__half2*)&w2.w);
        M0 = __hmax2(M0, *(__half2*)&w3.x); M1 = __hmax2(M1, *(__half2*)&w3.y);
        M2 = __hmax2(M2, *(__half2*)&w3.z); M3 = __hmax2(M3, *(__half2*)&w3.w);
    }
    #pragma unroll
    for (int k0 = 4; k0 < KNBR; k0 += 4) {
        uint4 w0, w1, w2, w3;
        LDG16(w0, D + (size_t)sp[k0 + 0] * 1024 + coff);
        LDG16(w1, D + (size_t)sp[k0 + 1] * 1024 + coff);
        LDG16(w2, D + (size_t)sp[k0 + 2] * 1024 + coff);
        LDG16(w3, D + (size_t)sp[k0 + 3] * 1024 + coff);
        M0 = __hmax2(M0, *(__half2*)&w0.x); M1 = __hmax2(M1, *(__half2*)&w0.y);
        M2 = __hmax2(M2, *(__half2*)&w0.z); M3 = __hmax2(M3, *(__half2*)&w0.w);
        M0 = __hmax2(M0, *(__half2*)&w1.x); M1 = __hmax2(M1, *(__half2*)&w1.y);
        M2 = __hmax2(M2, *(__half2*)&w1.z); M3 = __hmax2(M3, *(__half2*)&w1.w);
        M0 = __hmax2(M0, *(__half2*)&w2.x); M1 = __hmax2(M1, *(__half2*)&w2.y);
        M2 = __hmax2(M2, *(__half2*)&w2.z); M3 = __hmax2(M3, *(__half2*)&w2.w);
        M0 = __hmax2(M0, *(__half2*)&w3.x); M1 = __hmax2(M1, *(__half2*)&w3.y);
        M2 = __hmax2(M2, *(__half2*)&w3.z); M3 = __hmax2(M3, *(__half2*)&w3.w);
    }

    // add C (exact fp32 adds of fp16 values), relu
    uint4 cw = *(const uint4*)(D + (size_t)n * 1024 + 512 + coff);
    float2 c0 = __half22float2(*(__half2*)&cw.x);
    float2 c1 = __half22float2(*(__half2*)&cw.y);
    float2 c2 = __half22float2(*(__half2*)&cw.z);
    float2 c3 = __half22float2(*(__half2*)&cw.w);
    float2 m0 = __half22float2(M0);
    float2 m1 = __half22float2(M1);
    float2 m2 = __half22float2(M2);
    float2 m3 = __half22float2(M3);

    float4 r0, r1;
    r0.x = fmaxf(m0.x + c0.x, 0.0f);  r0.y = fmaxf(m0.y + c0.y, 0.0f);
    r0.z = fmaxf(m1.x + c1.x, 0.0f);  r0.w = fmaxf(m1.y + c1.y, 0.0f);
    r1.x = fmaxf(m2.x + c2.x, 0.0f);  r1.y = fmaxf(m2.y + c2.y, 0.0f);
    r1.z = fmaxf(m3.x + c3.x, 0.0f);  r1.w = fmaxf(m3.y + c3.y, 0.0f);

    float* op = out + (size_t)n * OUTLD + out_off + l64 * 8;
    *(float4*)(op)     = r0;
    *(float4*)(op + 4) = r1;

    if (write_xh) {
        uint4 hx;
        *(__half2*)&hx.x = __floats2half2_rn(r0.x, r0.y);
        *(__half2*)&hx.y = __floats2half2_rn(r0.z, r0.w);
        *(__half2*)&hx.z = __floats2half2_rn(r1.x, r1.y);
        *(__half2*)&hx.w = __floats2half2_rn(r1.z, r1.w);
        *(uint4*)(Xh + (size_t)n * LDIM + l64 * 8) = hx;
    }
}

// ---------------------------------------------------------------------------
extern "C" void kernel_launch(void* const* d_in, const int* in_sizes, int n_in,
                              void* d_out, int out_size)
{
    const float* rois   = (const float*)d_in[0];
    const float* pooled = (const float*)d_in[1];
    const int*   edge   = (const int*)  d_in[2];   // (2, 65536): row 0 = src
    const float* gW1    = (const float*)d_in[3];
    const float* gb1    = (const float*)d_in[4];
    const float* gW2    = (const float*)d_in[5];
    const float* gb2    = (const float*)d_in[6];
    const float* fcW[3] = {(const float*)d_in[7], (const float*)d_in[9],  (const float*)d_in[11]};
    const float* fcb[3] = {(const float*)d_in[8], (const float*)d_in[10], (const float*)d_in[12]};
    float* out = (float*)d_out;

    const int* src = edge;

    float *biasL;
    __half *D, *X0h, *Xh, *Wh, *Wl;
    cudaGetSymbolAddress((void**)&D,     g_D);
    cudaGetSymbolAddress((void**)&biasL, g_biasL);
    cudaGetSymbolAddress((void**)&X0h,   g_X0h);
    cudaGetSymbolAddress((void**)&Xh,    g_Xh);
    cudaGetSymbolAddress((void**)&Wh,    g_Wh);
    cudaGetSymbolAddress((void**)&Wl,    g_Wl);

    cudaFuncSetAttribute(gemm_mma, cudaFuncAttributeMaxDynamicSharedMemorySize, GEMM_SMEM);
    cudaFuncSetAttribute(geo_pre,  cudaFuncAttributeMaxDynamicSharedMemorySize, GEO_SMEM);

    // 1) fused geo prologue
    geo_pre<<<NNODES / GEO_NODES, 128, GEO_SMEM>>>(
        rois, pooled, gW1, gb1, gW2, gb2, out, X0h);

    // 2) all weight prep (independent of activations)
    prep_w3<<<dim3(1024, 3), 256>>>(
        fcW[0], fcb[0], fcW[1], fcb[1], fcW[2], fcb[2], Wh, Wl, biasL);

    // 3) three EdgeConv layers
    const int Kin[3]    = {INDIM, LDIM, LDIM};
    const int outOff[3] = {384, 384 + 512, 384 + 1024};

    for (int l = 0; l < 3; l++) {
        const __half* Ain = (l == 0) ? X0h : Xh;
        gemm_mma<<<dim3(1024 / 128, NNODES / 128), 256, GEMM_SMEM>>>(
            Ain, Wh + (size_t)l * WSTRIDE, Wl + (size_t)l * WSTRIDE,
            biasL + l * 1024, D, Kin[l]);

        aggregate<<<NNODES / 4, 256>>>(D, src, Xh, out, outOff[l], l < 2 ? 1 : 0);
    }
}

// round 16
// speedup vs baseline: 1.8011x; 1.0337x over previous
#include <cuda_runtime.h>
#include <cuda_bf16.h>
#include <cuda_fp16.h>
#include <cstdint>

// Problem constants
#define NNODES 4096       // B*N = 8*512
#define KNBR   16
#define CPOOL  256
#define GDIM   128
#define INDIM  384        // CPOOL + GDIM
#define LDIM   512
#define OUTLD  1920       // 384 + 3*512
#define WSTRIDE (1024 * 512)

// ---------------- device scratch (no allocations allowed) ----------------
__device__ float g_biasL[3 * 1024];
__device__ __align__(16) __half g_D  [NNODES * 1024];
__device__ __align__(16) __half g_X0h[NNODES * INDIM];
__device__ __align__(16) __half g_Xh [NNODES * LDIM];
__device__ __align__(16) __half g_Wh [3 * WSTRIDE];
__device__ __align__(16) __half g_Wl [3 * WSTRIDE];

// ======================= helpers =======================
__device__ __forceinline__ uint32_t smem_u32(const void* p) {
    uint32_t a;
    asm("{ .reg .u64 t; cvta.to.shared.u64 t, %1; cvt.u32.u64 %0, t; }"
        : "=r"(a) : "l"(p));
    return a;
}
__device__ __forceinline__ uint32_t sw128(uint32_t o) {  // SW128 swizzle, 128B rows
    return o ^ ((o >> 3) & 0x70);
}
__device__ __forceinline__ void cp16(uint32_t dst, const void* src) {
    asm volatile("cp.async.cg.shared.global [%0], [%1], 16;" :: "r"(dst), "l"(src));
}
#define CP_COMMIT() asm volatile("cp.async.commit_group;" ::: "memory")
#define CP_WAIT(n)  asm volatile("cp.async.wait_group %0;" :: "n"(n) : "memory")

#define LDSM4(r, a) \
    asm volatile("ldmatrix.sync.aligned.m8n8.x4.shared.b16 {%0,%1,%2,%3}, [%4];" \
        : "=r"((r)[0]), "=r"((r)[1]), "=r"((r)[2]), "=r"((r)[3]) : "r"(a))

#define MMAF16(d, a, b0, b1) \
    asm volatile("mma.sync.aligned.m16n8k16.row.col.f32.f16.f16.f32 " \
        "{%0,%1,%2,%3}, {%4,%5,%6,%7}, {%8,%9}, {%0,%1,%2,%3};" \
        : "+f"((d)[0]), "+f"((d)[1]), "+f"((d)[2]), "+f"((d)[3]) \
        : "r"((a)[0]), "r"((a)[1]), "r"((a)[2]), "r"((a)[3]), "r"(b0), "r"(b1))

// forced 16B non-coherent load
#define LDG16(v, ptr) \
    asm volatile("ld.global.nc.v4.u32 {%0,%1,%2,%3}, [%4];" \
        : "=r"((v).x), "=r"((v).y), "=r"((v).z), "=r"((v).w) : "l"(ptr))

// ======================= mma.sync GEMM (fp16, 2-pass, BK=64) ===============
// D(4096 x 1024, fp16) = X(4096 x Kin) @ W(1024 x Kin)^T + bias
// A = activations rounded to fp16; W split into fp16 hi + lo (exact).
// D = A*Wh + A*Wl, fp32 accumulation, fp16 store.
// CTA tile 128x128, BK=64, 8 warps (warp tile 32x64), cp.async double buffer.
// smem per stage (48KB): A | Bh | Bl, each 128 rows x 128B, SW128.
#define ARR_BYTES (128 * 128)               // 16384
#define STG_BYTES (3 * ARR_BYTES)           // 49152
#define GEMM_SMEM (2 * STG_BYTES)           // 98304

__global__ __launch_bounds__(256) void gemm_mma(
    const __half* __restrict__ A,
    const __half* __restrict__ Bh, const __half* __restrict__ Bl,
    const float* __restrict__ bias,
    __half* __restrict__ C,     // ldc = 1024, fp16
    int Kin)
{
    extern __shared__ char smem[];
    const uint32_t sb  = smem_u32(smem);
    const int tid  = threadIdx.x;
    const int lane = tid & 31;
    const int wid  = tid >> 5;
    const int bm   = blockIdx.y * 128;
    const int bn   = blockIdx.x * 128;
    const int m0   = (wid & 3) * 32;     // warp m-offset in tile
    const int n0   = (wid >> 2) * 64;    // warp n-offset in tile

    // cp.async chunk mapping: 128 rows x 8 segs(16B) per array = 1024 chunks,
    // 4 per thread (rows rc, rc+32, rc+64, rc+96)
    const int rc = tid >> 3;             // 0..31
    const int sc = tid & 7;              // 0..7

    const __half* gsrc[3] = { A, Bh, Bl };
    const int grow0[3] = { bm, bn, bn };

    uint32_t soff[3][4];
    #pragma unroll
    for (int a = 0; a < 3; a++)
        #pragma unroll
        for (int it = 0; it < 4; it++)
            soff[a][it] = a * ARR_BYTES +
                sw128((uint32_t)((rc + 32 * it) * 128 + sc * 16));

    const int nk = Kin / 64;

    // ---- issue stage 0 ----
    {
        const uint32_t bufb = sb;
        #pragma unroll
        for (int a = 0; a < 3; a++)
            #pragma unroll
            for (int it = 0; it < 4; it++)
                cp16(bufb + soff[a][it],
                     gsrc[a] + (size_t)(grow0[a] + rc + 32 * it) * Kin + sc * 8);
        CP_COMMIT();
    }

    float acc[2][8][4];
    #pragma unroll
    for (int i = 0; i < 2; i++)
        #pragma unroll
        for (int j = 0; j < 8; j++)
            #pragma unroll
            for (int q = 0; q < 4; q++)
                acc[i][j][q] = 0.0f;

    // ldmatrix per-lane address components
    const int a_row = lane & 15;
    const int a_kh  = (lane >> 4) & 1;
    const int b_row = ((lane >> 4) << 3) + (lane & 7);
    const int b_kh  = (lane >> 3) & 1;

    for (int s = 0; s < nk; s++) {
        const uint32_t bufb = sb + (uint32_t)(s & 1) * STG_BYTES;

        if (s + 1 < nk) {
            const uint32_t nb = sb + (uint32_t)((s + 1) & 1) * STG_BYTES;
            const int kb = (s + 1) * 64;
            #pragma unroll
            for (int a = 0; a < 3; a++)
                #pragma unroll
                for (int it = 0; it < 4; it++)
                    cp16(nb + soff[a][it],
                         gsrc[a] + (size_t)(grow0[a] + rc + 32 * it) * Kin + kb + sc * 8);
            CP_COMMIT();
            CP_WAIT(1);
        } else {
            CP_WAIT(0);
        }
        __syncthreads();

        #pragma unroll
        for (int kk = 0; kk < 4; kk++) {
            uint32_t fa[2][4];
            #pragma unroll
            for (int mt = 0; mt < 2; mt++) {
                const uint32_t off =
                    sw128((uint32_t)((m0 + mt * 16 + a_row) * 128 + kk * 32 + a_kh * 16));
                LDSM4(fa[mt], bufb + 0 * ARR_BYTES + off);
            }
            uint32_t fbh[4][4], fbl[4][4];
            #pragma unroll
            for (int nt = 0; nt < 4; nt++) {
                const uint32_t off =
                    sw128((uint32_t)((n0 + nt * 16 + b_row) * 128 + kk * 32 + b_kh * 16));
                LDSM4(fbh[nt], bufb + 1 * ARR_BYTES + off);
                LDSM4(fbl[nt], bufb + 2 * ARR_BYTES + off);
            }
            #pragma unroll
            for (int mt = 0; mt < 2; mt++) {
                #pragma unroll
                for (int ni = 0; ni < 8; ni++) {
                    const uint32_t bh0 = fbh[ni >> 1][(ni & 1) * 2];
                    const uint32_t bh1 = fbh[ni >> 1][(ni & 1) * 2 + 1];
                    const uint32_t bl0 = fbl[ni >> 1][(ni & 1) * 2];
                    const uint32_t bl1 = fbl[ni >> 1][(ni & 1) * 2 + 1];
                    MMAF16(acc[mt][ni], fa[mt], bh0, bh1);
                    MMAF16(acc[mt][ni], fa[mt], bl0, bl1);
                }
            }
        }
        __syncthreads();
    }

    // ---- epilogue: write D (fp16) with bias ----
    #pragma unroll
    for (int mt = 0; mt < 2; mt++) {
        const int r = bm + m0 + mt * 16 + (lane >> 2);
        #pragma unroll
        for (int ni = 0; ni < 8; ni++) {
            const int col = bn + n0 + ni * 8 + (lane & 3) * 2;
            const float b0 = bias[col], b1 = bias[col + 1];
            __half2 v0 = __floats2half2_rn(acc[mt][ni][0] + b0, acc[mt][ni][1] + b1);
            __half2 v1 = __floats2half2_rn(acc[mt][ni][2] + b0, acc[mt][ni][3] + b1);
            *(__half2*)(C + (size_t)r * 1024 + col)       = v0;
            *(__half2*)(C + (size_t)(r + 8) * 1024 + col) = v1;
        }
    }
}

// ======================= fused geo prologue =======================
#define GEO_NODES 16
#define GEO_W2T   0
#define GEO_W1    (128 * 129)
#define GEO_B1    (GEO_W1 + 896)
#define GEO_B2    (GEO_B1 + 128)
#define GEO_ROI   (GEO_B2 + 128)
#define GEO_H     (GEO_ROI + 128)
#define GEO_SMEMF (GEO_H + GEO_NODES * 132)
#define GEO_SMEM  (GEO_SMEMF * 4)

__global__ __launch_bounds__(128) void geo_pre(
    const float* __restrict__ rois,
    const float* __restrict__ pooled,
    const float* __restrict__ gW1, const float* __restrict__ gb1,
    const float* __restrict__ gW2, const float* __restrict__ gb2,
    float* __restrict__ out,
    __half* __restrict__ X0h)
{
    extern __shared__ float s[];
    const int tid = threadIdx.x;
    const int n0  = blockIdx.x * GEO_NODES;

    for (int i = tid; i < 128 * 128; i += 128) {
        int r = i >> 7, c = i & 127;
        s[GEO_W2T + c * 129 + r] = gW2[i];
    }
    for (int i = tid; i < 896; i += 128) s[GEO_W1 + i] = gW1[i];
    s[GEO_B1 + tid] = gb1[tid];
    s[GEO_B2 + tid] = gb2[tid];
    if (tid < GEO_NODES * 7) {
        int node = tid / 7, j = tid - node * 7;
        s[GEO_ROI + node * 8 + j] = rois[(size_t)(n0 + node) * 7 + j];
    }
    __syncthreads();

    #pragma unroll
    for (int node = 0; node < GEO_NODES; node++) {
        float a = s[GEO_B1 + tid];
        #pragma unroll
        for (int j = 0; j < 7; j++)
            a = fmaf(s[GEO_W1 + tid * 7 + j], s[GEO_ROI + node * 8 + j], a);
        s[GEO_H + node * 132 + tid] = fmaxf(a, 0.0f);
    }
    __syncthreads();

    float acc[GEO_NODES];
    #pragma unroll
    for (int node = 0; node < GEO_NODES; node++) acc[node] = s[GEO_B2 + tid];

    #pragma unroll 8
    for (int j = 0; j < 128; j += 4) {
        const float w0 = s[GEO_W2T + (j + 0) * 129 + tid];
        const float w1 = s[GEO_W2T + (j + 1) * 129 + tid];
        const float w2 = s[GEO_W2T + (j + 2) * 129 + tid];
        const float w3 = s[GEO_W2T + (j + 3) * 129 + tid];
        #pragma unroll
        for (int node = 0; node < GEO_NODES; node++) {
            float4 h = *(const float4*)&s[GEO_H + node * 132 + j];
            float a = acc[node];
            a = fmaf(w0, h.x, a);
            a = fmaf(w1, h.y, a);
            a = fmaf(w2, h.z, a);
            a = fmaf(w3, h.w, a);
            acc[node] = a;
        }
    }

    #pragma unroll
    for (int node = 0; node < GEO_NODES; node++) {
        const int n = n0 + node;
        const float g = fmaxf(acc[node], 0.0f);
        out[(size_t)n * OUTLD + CPOOL + tid] = g;
        X0h[(size_t)n * INDIM + CPOOL + tid] = __float2half_rn(g);

        const float v0 = pooled[(size_t)n * CPOOL + tid];
        const float v1 = pooled[(size_t)n * CPOOL + tid + 128];
        out[(size_t)n * OUTLD + tid]       = v0;
        out[(size_t)n * OUTLD + tid + 128] = v1;
        X0h[(size_t)n * INDIM + tid]       = __float2half_rn(v0);
        X0h[(size_t)n * INDIM + tid + 128] = __float2half_rn(v1);
    }
}

// ======================= weight prep (all 3 layers, fp16 hi/lo) ============
__global__ void prep_w3(
    const float* __restrict__ W0, const float* __restrict__ b0,
    const float* __restrict__ W1, const float* __restrict__ b1,
    const float* __restrict__ W2, const float* __restrict__ b2,
    __half* __restrict__ Wh, __half* __restrict__ Wl,
    float* __restrict__ biasL)
{
    const int layer = blockIdx.y;
    const float* W = (layer == 0) ? W0 : (layer == 1) ? W1 : W2;
    const float* b = (layer == 0) ? b0 : (layer == 1) ? b1 : b2;
    const int Kin  = (layer == 0) ? INDIM : LDIM;

    __half* wh = Wh + (size_t)layer * WSTRIDE;
    __half* wl = Wl + (size_t)layer * WSTRIDE;

    int idx = blockIdx.x * blockDim.x + threadIdx.x;
    if (idx < 512 * Kin) {
        int r = idx / Kin, c = idx % Kin;
        float vl = W[(size_t)r * 2 * Kin + c];
        float vr = W[(size_t)r * 2 * Kin + Kin + c];
        float d  = vr - vl;

        __half h = __float2half_rn(vl);
        wh[(size_t)r * Kin + c] = h;
        wl[(size_t)r * Kin + c] = __float2half_rn(vl - __half2float(h));
        h = __float2half_rn(d);
        wh[(size_t)(512 + r) * Kin + c] = h;
        wl[(size_t)(512 + r) * Kin + c] = __float2half_rn(d - __half2float(h));
    }
    if (idx < 512) {
        biasL[layer * 1024 + idx]       = 0.0f;
        biasL[layer * 1024 + 512 + idx] = b[idx];
    }
}

// ---------------- aggregation: fp16 hmax reduction ------------------------
__global__ __launch_bounds__(256) void aggregate(
    const __half* __restrict__ D,
    const int*   __restrict__ src,
    __half* __restrict__ Xh,         // 4096 x 512
    float* __restrict__ out,         // 4096 x 1920
    int out_off, int write_xh)
{
    const int n   = blockIdx.x * 4 + (threadIdx.x >> 6);
    const int l64 = threadIdx.x & 63;      // 0..63, owns 8 halves

    const int* sp = src + n * KNBR;
    const size_t coff = (size_t)l64 * 8;

    __half2 M0, M1, M2, M3;
    {
        uint4 w0, w1, w2, w3;
        LDG16(w0, D + (size_t)sp[0] * 1024 + coff);
        LDG16(w1, D + (size_t)sp[1] * 1024 + coff);
        LDG16(w2, D + (size_t)sp[2] * 1024 + coff);
        LDG16(w3, D + (size_t)sp[3] * 1024 + coff);
        M0 = *(__half2*)&w0.x;  M1 = *(__half2*)&w0.y;
        M2 = *(__half2*)&w0.z;  M3 = *(__half2*)&w0.w;
        M0 = __hmax2(M0, *(__half2*)&w1.x); M1 = __hmax2(M1, *(__half2*)&w1.y);
        M2 = __hmax2(M2, *(__half2*)&w1.z); M3 = __hmax2(M3, *(__half2*)&w1.w);
        M0 = __hmax2(M0, *(__half2*)&w2.x); M1 = __hmax2(M1, *(__half2*)&w2.y);
        M2 = __hmax2(M2, *(__half2*)&w2.z); M3 = __hmax2(M3, *(__half2*)&w2.w);
        M0 = __hmax2(M0, *(__half2*)&w3.x); M1 = __hmax2(M1, *(__half2*)&w3.y);
        M2 = __hmax2(M2, *(__half2*)&w3.z); M3 = __hmax2(M3, *(__half2*)&w3.w);
    }
    #pragma unroll
    for (int k0 = 4; k0 < KNBR; k0 += 4) {
        uint4 w0, w1, w2, w3;
        LDG16(w0, D + (size_t)sp[k0 + 0] * 1024 + coff);
        LDG16(w1, D + (size_t)sp[k0 + 1] * 1024 + coff);
        LDG16(w2, D + (size_t)sp[k0 + 2] * 1024 + coff);
        LDG16(w3, D + (size_t)sp[k0 + 3] * 1024 + coff);
        M0 = __hmax2(M0, *(__half2*)&w0.x); M1 = __hmax2(M1, *(__half2*)&w0.y);
        M2 = __hmax2(M2, *(__half2*)&w0.z); M3 = __hmax2(M3, *(__half2*)&w0.w);
        M0 = __hmax2(M0, *(__half2*)&w1.x); M1 = __hmax2(M1, *(__half2*)&w1.y);
        M2 = __hmax2(M2, *(__half2*)&w1.z); M3 = __hmax2(M3, *(__half2*)&w1.w);
        M0 = __hmax2(M0, *(__half2*)&w2.x); M1 = __hmax2(M1, *(__half2*)&w2.y);
        M2 = __hmax2(M2, *(__half2*)&w2.z); M3 = __hmax2(M3, *(__half2*)&w2.w);
        M0 = __hmax2(M0, *(__half2*)&w3.x); M1 = __hmax2(M1, *(__half2*)&w3.y);
        M2 = __hmax2(M2, *(__half2*)&w3.z); M3 = __hmax2(M3, *(__half2*)&w3.w);
    }

    uint4 cw = *(const uint4*)(D + (size_t)n * 1024 + 512 + coff);
    float2 c0 = __half22float2(*(__half2*)&cw.x);
    float2 c1 = __half22float2(*(__half2*)&cw.y);
    float2 c2 = __half22float2(*(__half2*)&cw.z);
    float2 c3 = __half22float2(*(__half2*)&cw.w);
    float2 m0 = __half22float2(M0);
    float2 m1 = __half22float2(M1);
    float2 m2 = __half22float2(M2);
    float2 m3 = __half22float2(M3);

    float4 r0, r1;
    r0.x = fmaxf(m0.x + c0.x, 0.0f);  r0.y = fmaxf(m0.y + c0.y, 0.0f);
    r0.z = fmaxf(m1.x + c1.x, 0.0f);  r0.w = fmaxf(m1.y + c1.y, 0.0f);
    r1.x = fmaxf(m2.x + c2.x, 0.0f);  r1.y = fmaxf(m2.y + c2.y, 0.0f);
    r1.z = fmaxf(m3.x + c3.x, 0.0f);  r1.w = fmaxf(m3.y + c3.y, 0.0f);

    float* op = out + (size_t)n * OUTLD + out_off + l64 * 8;
    *(float4*)(op)     = r0;
    *(float4*)(op + 4) = r1;

    if (write_xh) {
        uint4 hx;
        *(__half2*)&hx.x = __floats2half2_rn(r0.x, r0.y);
        *(__half2*)&hx.y = __floats2half2_rn(r0.z, r0.w);
        *(__half2*)&hx.z = __floats2half2_rn(r1.x, r1.y);
        *(__half2*)&hx.w = __floats2half2_rn(r1.z, r1.w);
        *(uint4*)(Xh + (size_t)n * LDIM + l64 * 8) = hx;
    }
}

// ---------------------------------------------------------------------------
extern "C" void kernel_launch(void* const* d_in, const int* in_sizes, int n_in,
                              void* d_out, int out_size)
{
    const float* rois   = (const float*)d_in[0];
    const float* pooled = (const float*)d_in[1];
    const int*   edge   = (const int*)  d_in[2];   // (2, 65536): row 0 = src
    const float* gW1    = (const float*)d_in[3];
    const float* gb1    = (const float*)d_in[4];
    const float* gW2    = (const float*)d_in[5];
    const float* gb2    = (const float*)d_in[6];
    const float* fcW[3] = {(const float*)d_in[7], (const float*)d_in[9],  (const float*)d_in[11]};
    const float* fcb[3] = {(const float*)d_in[8], (const float*)d_in[10], (const float*)d_in[12]};
    float* out = (float*)d_out;

    const int* src = edge;

    float *biasL;
    __half *D, *X0h, *Xh, *Wh, *Wl;
    cudaGetSymbolAddress((void**)&D,     g_D);
    cudaGetSymbolAddress((void**)&biasL, g_biasL);
    cudaGetSymbolAddress((void**)&X0h,   g_X0h);
    cudaGetSymbolAddress((void**)&Xh,    g_Xh);
    cudaGetSymbolAddress((void**)&Wh,    g_Wh);
    cudaGetSymbolAddress((void**)&Wl,    g_Wl);

    cudaFuncSetAttribute(gemm_mma, cudaFuncAttributeMaxDynamicSharedMemorySize, GEMM_SMEM);
    cudaFuncSetAttribute(geo_pre,  cudaFuncAttributeMaxDynamicSharedMemorySize, GEO_SMEM);

    // 1) fused geo prologue
    geo_pre<<<NNODES / GEO_NODES, 128, GEO_SMEM>>>(
        rois, pooled, gW1, gb1, gW2, gb2, out, X0h);

    // 2) all weight prep (independent of activations)
    prep_w3<<<dim3(1024, 3), 256>>>(
        fcW[0], fcb[0], fcW[1], fcb[1], fcW[2], fcb[2], Wh, Wl, biasL);

    // 3) three EdgeConv layers
    const int Kin[3]    = {INDIM, LDIM, LDIM};
    const int outOff[3] = {384, 384 + 512, 384 + 1024};

    for (int l = 0; l < 3; l++) {
        const __half* Ain = (l == 0) ? X0h : Xh;
        gemm_mma<<<dim3(1024 / 128, NNODES / 128), 256, GEMM_SMEM>>>(
            Ain, Wh + (size_t)l * WSTRIDE, Wl + (size_t)l * WSTRIDE,
            biasL + l * 1024, D, Kin[l]);

        aggregate<<<NNODES / 4, 256>>>(D, src, Xh, out, outOff[l], l < 2 ? 1 : 0);
    }
}